// round 15
// baseline (speedup 1.0000x reference)
#include <cuda_runtime.h>
#include <math.h>
#include <stdint.h>

#define BB 24
#define SS 512
#define DD 512
#define HH 8
#define DKH 64
#define DFF 2048
#define FC1D 512
#define FC2D 256
#define NTOK (BB*SS)
#define HR 7   /* H - HS routed heads */

// ------------------------- scratch (device globals) -------------------------
__device__ __align__(16) float g_x[NTOK*DD];
__device__ __align__(16) float g_y[NTOK*DD];
__device__ __align__(16) float g_ql[NTOK*DD];
__device__ __align__(16) float g_vl[NTOK*DD];
__device__ __align__(16) float g_att[NTOK*DD];
__device__ __align__(16) float g_x1[NTOK*DD];
__device__ __align__(16) float g_h2[NTOK*FC2D];
__device__ float g_dyn[NTOK*HR];
__device__ float g_rmask[BB*HH];

// packed bf16 mirrors (u32 = pair of bf16 along the consumer-K dim)
__device__ __align__(16) uint32_t g_xp[NTOK*DD/2];
__device__ __align__(16) uint32_t g_yp[NTOK*DD/2];
__device__ __align__(16) uint32_t g_qembp[NTOK*DD/2];
__device__ __align__(16) uint32_t g_qlp[NTOK*DD/2];
__device__ __align__(16) uint32_t g_ctxp[NTOK*DD/2];
__device__ __align__(16) uint32_t g_x1p[NTOK*DD/2];
__device__ __align__(16) uint32_t g_ffp[NTOK*DFF/2];
__device__ __align__(16) uint32_t g_hcatp[NTOK*DD];      // 2D/2 = D u32 per row
__device__ __align__(16) uint32_t g_h1p[NTOK*FC1D/2];

// packed weights
__device__ __align__(16) uint32_t g_Wqp[6*(DD/2)*DD];
__device__ __align__(16) uint32_t g_Wvp[6*(DD/2)*DD];
__device__ __align__(16) uint32_t g_Wop[6*(DD/2)*DD];
__device__ __align__(16) uint32_t g_W1p[6*(DD/2)*DFF];
__device__ __align__(16) uint32_t g_W2p[6*(DFF/2)*DD];
__device__ __align__(16) uint32_t g_ow1p[DD*FC1D];
__device__ __align__(16) uint32_t g_ow2p[(FC1D/2)*FC2D];

// ------------------------- helpers -------------------------
__device__ __forceinline__ uint32_t packbf(float lo, float hi) {
    uint32_t r;
    asm("cvt.rn.bf16x2.f32 %0, %1, %2;" : "=r"(r) : "f"(hi), "f"(lo));  // first src -> high half
    return r;
}

__device__ __forceinline__ void mma_bf16(float c[4], const uint32_t a[4], const uint32_t b[2]) {
    asm volatile(
        "mma.sync.aligned.m16n8k16.row.col.f32.bf16.bf16.f32 "
        "{%0,%1,%2,%3}, {%4,%5,%6,%7}, {%8,%9}, {%0,%1,%2,%3};"
        : "+f"(c[0]), "+f"(c[1]), "+f"(c[2]), "+f"(c[3])
        : "r"(a[0]), "r"(a[1]), "r"(a[2]), "r"(a[3]), "r"(b[0]), "r"(b[1]));
}

__device__ __forceinline__ void cp16(void* dst, const void* src) {
    uint32_t d = (uint32_t)__cvta_generic_to_shared(dst);
    asm volatile("cp.async.cg.shared.global [%0], [%1], 16;" :: "r"(d), "l"(src));
}

// ------------------------- vectorized weight packing -------------------------
// W[K][N] f32 -> out[K/2][N] u32 ; pairs along K. Works on layer-stacked weights
// because per-layer K is even, so pairs never cross layer boundaries.
__global__ void pack_mat4(const float* __restrict__ W, uint32_t* __restrict__ out,
                          int KP, int N4) {
    size_t idx = (size_t)blockIdx.x * 256 + threadIdx.x;
    if (idx >= (size_t)KP * N4) return;
    int n4 = (int)(idx % N4);
    size_t kp = idx / N4;
    int N = N4 * 4;
    float4 r0 = *(const float4*)&W[(2 * kp) * N + (size_t)n4 * 4];
    float4 r1 = *(const float4*)&W[(2 * kp + 1) * N + (size_t)n4 * 4];
    uint4 o;
    o.x = packbf(r0.x, r1.x);
    o.y = packbf(r0.y, r1.y);
    o.z = packbf(r0.z, r1.z);
    o.w = packbf(r0.w, r1.w);
    ((uint4*)out)[idx] = o;
}

// ------------------------- embeddings -------------------------
__global__ void embed_kernel(const int* __restrict__ qd, const int* __restrict__ tg,
                             const int* __restrict__ pid,
                             const float* __restrict__ qtab, const float* __restrict__ qatab,
                             const float* __restrict__ qdtab, const float* __restrict__ qadtab,
                             const float* __restrict__ pdtab) {
    int t = blockIdx.x;
    int tid = threadIdx.x;              // blockDim = 256
    int d0 = 2 * tid, d1 = d0 + 1;
    int qi = qd[t], ti = tg[t], pi = pid[t];
    float ps = pdtab[pi];
    float qe0 = qtab[(size_t)qi*DD + d0], qe1 = qtab[(size_t)qi*DD + d1];
    float qv0 = qdtab[(size_t)qi*DD + d0], qv1 = qdtab[(size_t)qi*DD + d1];
    float em0 = qe0 + ps * qv0, em1 = qe1 + ps * qv1;
    float qa0 = qatab[(size_t)ti*DD + d0] + qe0 + ps * (qadtab[(size_t)ti*DD + d0] + qv0);
    float qa1 = qatab[(size_t)ti*DD + d1] + qe1 + ps * (qadtab[(size_t)ti*DD + d1] + qv1);
    g_x[(size_t)t*DD + d0] = em0; g_x[(size_t)t*DD + d1] = em1;
    g_y[(size_t)t*DD + d0] = qa0; g_y[(size_t)t*DD + d1] = qa1;
    g_xp[(size_t)t*(DD/2) + tid]    = packbf(em0, em1);
    g_yp[(size_t)t*(DD/2) + tid]    = packbf(qa0, qa1);
    g_qembp[(size_t)t*(DD/2) + tid] = packbf(em0, em1);
}

// ------------------------- bf16 tensor-core GEMM, 2-stage cp.async pipeline -------------------------
__global__ __launch_bounds__(256) void gemm_bf16(const uint32_t* __restrict__ Apk,
                                                 const uint32_t* __restrict__ Bpk,
                                                 const float* __restrict__ bias,
                                                 float* __restrict__ C, uint32_t* __restrict__ Cpk,
                                                 int M, int N, int K, int relu) {
    __shared__ uint32_t As[2][128][20];
    __shared__ uint32_t Bs[2][16][136];
    int tid = threadIdx.x;
    int lane = tid & 31, warp = tid >> 5;
    int wm = warp >> 1, wn = warp & 1;
    int g = lane >> 2, tg = lane & 3;
    int m0 = blockIdx.y * 128, n0 = blockIdx.x * 128;
    int KP = K >> 1;
    int NK = K >> 5;

    float acc[2][8][4];
    #pragma unroll
    for (int i = 0; i < 2; i++)
        #pragma unroll
        for (int j = 0; j < 8; j++)
            #pragma unroll
            for (int r = 0; r < 4; r++) acc[i][j][r] = 0.0f;

#define LOAD_TILES(st, it) do {                                                   \
    int base = (it) * 16;                                                         \
    _Pragma("unroll")                                                             \
    for (int p = 0; p < 2; p++) {                                                 \
        int id = tid + p * 256; int r = id >> 2; int c4 = (id & 3) * 4;           \
        cp16(&As[st][r][c4], &Apk[(size_t)(m0 + r) * KP + base + c4]);            \
    }                                                                             \
    _Pragma("unroll")                                                             \
    for (int p = 0; p < 2; p++) {                                                 \
        int id = tid + p * 256; int r = id >> 5; int c4 = (id & 31) * 4;          \
        cp16(&Bs[st][r][c4], &Bpk[(size_t)(base + r) * N + n0 + c4]);             \
    }                                                                             \
    asm volatile("cp.async.commit_group;");                                       \
} while (0)

    LOAD_TILES(0, 0);
    int s = 0;
    for (int it = 0; it < NK; it++) {
        if (it + 1 < NK) {
            LOAD_TILES(s ^ 1, it + 1);
            asm volatile("cp.async.wait_group 1;");
        } else {
            asm volatile("cp.async.wait_group 0;");
        }
        __syncthreads();
        #pragma unroll
        for (int kk = 0; kk < 2; kk++) {
            int kb = kk * 8;
            uint32_t af[2][4], bf[8][2];
            #pragma unroll
            for (int i = 0; i < 2; i++) {
                int m = wm * 32 + i * 16;
                af[i][0] = As[s][m + g][kb + tg];
                af[i][1] = As[s][m + 8 + g][kb + tg];
                af[i][2] = As[s][m + g][kb + 4 + tg];
                af[i][3] = As[s][m + 8 + g][kb + 4 + tg];
            }
            #pragma unroll
            for (int j = 0; j < 8; j++) {
                int n = wn * 64 + j * 8 + g;
                bf[j][0] = Bs[s][kb + tg][n];
                bf[j][1] = Bs[s][kb + 4 + tg][n];
            }
            #pragma unroll
            for (int i = 0; i < 2; i++)
                #pragma unroll
                for (int j = 0; j < 8; j++)
                    mma_bf16(acc[i][j], af[i], bf[j]);
        }
        __syncthreads();
        s ^= 1;
    }
#undef LOAD_TILES

    #pragma unroll
    for (int i = 0; i < 2; i++) {
        int m = m0 + wm * 32 + i * 16 + g;
        #pragma unroll
        for (int j = 0; j < 8; j++) {
            int n = n0 + wn * 64 + j * 8 + tg * 2;
            float b0 = bias[n], b1 = bias[n + 1];
            float v0 = acc[i][j][0] + b0, v1 = acc[i][j][1] + b1;
            float v2 = acc[i][j][2] + b0, v3 = acc[i][j][3] + b1;
            if (relu) { v0 = fmaxf(v0, 0.f); v1 = fmaxf(v1, 0.f); v2 = fmaxf(v2, 0.f); v3 = fmaxf(v3, 0.f); }
            if (C) {
                C[(size_t)m * N + n]           = v0;
                C[(size_t)m * N + n + 1]       = v1;
                C[(size_t)(m + 8) * N + n]     = v2;
                C[(size_t)(m + 8) * N + n + 1] = v3;
            }
            if (Cpk) {
                Cpk[(size_t)m * (N >> 1) + (n >> 1)]       = packbf(v0, v1);
                Cpk[(size_t)(m + 8) * (N >> 1) + (n >> 1)] = packbf(v2, v3);
            }
        }
    }
}

// ------------------------- fused flash attention -------------------------
// One CTA = 128 query rows of one (b,h). 8 warps x 16 rows. Online softmax.
// K == Q (kq_same). Causal early-exit over 64-wide j-tiles. Writes g_ctxp packed.
// Token-row-0 (uniform softmax) is overwritten afterwards by row0_fix.
__global__ __launch_bounds__(256) void flash_attn(const float* __restrict__ vl, int strict) {
    int bh = blockIdx.y; int b = bh >> 3, h = bh & 7;
    int i0 = blockIdx.x * 128;
    __shared__ uint32_t Qs[128][36];   // [row][dkpair]
    __shared__ uint32_t Ks[64][36];    // [row][dkpair]  (same layout as Qs)
    __shared__ uint32_t Vs[32][72];    // [jpair][dk]
    int tid = threadIdx.x, lane = tid & 31, w = tid >> 5;
    int g = lane >> 2, tg = lane & 3;

    // load Q tile (coalesced, conflict-free)
    #pragma unroll
    for (int p = 0; p < 16; p++) {
        int id = tid + p * 256;
        int r = id >> 5, c = id & 31;
        Qs[r][c] = g_qlp[(size_t)(b * SS + i0 + r) * (DD/2) + h * 32 + c];
    }

    float oacc[8][4];
    #pragma unroll
    for (int d = 0; d < 8; d++)
        #pragma unroll
        for (int r = 0; r < 4; r++) oacc[d][r] = 0.0f;
    float m0 = -1e30f, m1 = -1e30f, l0 = 0.0f, l1 = 0.0f;

    int row0g = i0 + w * 16 + g;   // global seq row for c0/c1 of fragments
    int row1g = row0g + 8;

    int njt = 2 * blockIdx.x + 2;  // causal tile limit: j0 <= i0+127

    for (int jt = 0; jt < njt; jt++) {
        int j0 = jt * 64;
        __syncthreads();           // previous iter's K/V fully consumed
        // K tile: 64 rows x 32 dkpairs
        #pragma unroll
        for (int p = 0; p < 8; p++) {
            int id = tid + p * 256;
            int r = id >> 5, c = id & 31;
            Ks[r][c] = g_qlp[(size_t)(b * SS + j0 + r) * (DD/2) + h * 32 + c];
        }
        // V tile: pack fp32 rows pairs -> Vs[jpair][dk]
        #pragma unroll
        for (int p = 0; p < 2; p++) {
            int id = tid + p * 256;
            int jp = id >> 4, c = (id & 15) * 4;
            const float* v0p = &vl[(size_t)(b * SS + j0 + 2 * jp) * DD + h * DKH + c];
            const float* v1p = v0p + DD;
            float4 a = *(const float4*)v0p;
            float4 bb = *(const float4*)v1p;
            Vs[jp][c + 0] = packbf(a.x, bb.x);
            Vs[jp][c + 1] = packbf(a.y, bb.y);
            Vs[jp][c + 2] = packbf(a.z, bb.z);
            Vs[jp][c + 3] = packbf(a.w, bb.w);
        }
        __syncthreads();

        // ---- scores: S[16x64] per warp ----
        float sacc[8][4];
        #pragma unroll
        for (int jf = 0; jf < 8; jf++)
            #pragma unroll
            for (int r = 0; r < 4; r++) sacc[jf][r] = 0.0f;
        #pragma unroll
        for (int kc = 0; kc < 4; kc++) {
            uint32_t af[4];
            af[0] = Qs[w * 16 + g][kc * 8 + tg];
            af[1] = Qs[w * 16 + 8 + g][kc * 8 + tg];
            af[2] = Qs[w * 16 + g][kc * 8 + 4 + tg];
            af[3] = Qs[w * 16 + 8 + g][kc * 8 + 4 + tg];
            #pragma unroll
            for (int jf = 0; jf < 8; jf++) {
                uint32_t bf2[2];
                bf2[0] = Ks[jf * 8 + g][kc * 8 + tg];
                bf2[1] = Ks[jf * 8 + g][kc * 8 + 4 + tg];
                mma_bf16(sacc[jf], af, bf2);
            }
        }

        // ---- mask + scale, tile row-max ----
        float tm0 = -1e30f, tm1 = -1e30f;
        #pragma unroll
        for (int jf = 0; jf < 8; jf++) {
            int c0 = j0 + jf * 8 + 2 * tg;
            int c1 = c0 + 1;
            bool a00 = strict ? (c0 < row0g || (row0g == 0 && c0 == 0)) : (c0 <= row0g);
            bool a01 = strict ? (c1 < row0g) : (c1 <= row0g);
            bool a10 = strict ? (c0 < row1g) : (c0 <= row1g);
            bool a11 = strict ? (c1 < row1g) : (c1 <= row1g);
            sacc[jf][0] = a00 ? sacc[jf][0] * 0.125f : -1e30f;
            sacc[jf][1] = a01 ? sacc[jf][1] * 0.125f : -1e30f;
            sacc[jf][2] = a10 ? sacc[jf][2] * 0.125f : -1e30f;
            sacc[jf][3] = a11 ? sacc[jf][3] * 0.125f : -1e30f;
            tm0 = fmaxf(tm0, fmaxf(sacc[jf][0], sacc[jf][1]));
            tm1 = fmaxf(tm1, fmaxf(sacc[jf][2], sacc[jf][3]));
        }
        tm0 = fmaxf(tm0, __shfl_xor_sync(0xffffffffu, tm0, 1));
        tm0 = fmaxf(tm0, __shfl_xor_sync(0xffffffffu, tm0, 2));
        tm1 = fmaxf(tm1, __shfl_xor_sync(0xffffffffu, tm1, 1));
        tm1 = fmaxf(tm1, __shfl_xor_sync(0xffffffffu, tm1, 2));

        float nm0 = fmaxf(m0, tm0), nm1 = fmaxf(m1, tm1);
        float sc0 = expf(m0 - nm0), sc1 = expf(m1 - nm1);
        float ts0 = 0.0f, ts1 = 0.0f;
        #pragma unroll
        for (int jf = 0; jf < 8; jf++) {
            float p0 = expf(sacc[jf][0] - nm0);
            float p1 = expf(sacc[jf][1] - nm0);
            float p2 = expf(sacc[jf][2] - nm1);
            float p3 = expf(sacc[jf][3] - nm1);
            sacc[jf][0] = p0; sacc[jf][1] = p1; sacc[jf][2] = p2; sacc[jf][3] = p3;
            ts0 += p0 + p1; ts1 += p2 + p3;
        }
        ts0 += __shfl_xor_sync(0xffffffffu, ts0, 1);
        ts0 += __shfl_xor_sync(0xffffffffu, ts0, 2);
        ts1 += __shfl_xor_sync(0xffffffffu, ts1, 1);
        ts1 += __shfl_xor_sync(0xffffffffu, ts1, 2);
        l0 = l0 * sc0 + ts0;
        l1 = l1 * sc1 + ts1;
        m0 = nm0; m1 = nm1;
        #pragma unroll
        for (int d = 0; d < 8; d++) {
            oacc[d][0] *= sc0; oacc[d][1] *= sc0;
            oacc[d][2] *= sc1; oacc[d][3] *= sc1;
        }

        // ---- P @ V: C-frag of scores re-packed as A-frag ----
        #pragma unroll
        for (int kc = 0; kc < 4; kc++) {
            uint32_t af[4];
            af[0] = packbf(sacc[2*kc][0],   sacc[2*kc][1]);
            af[1] = packbf(sacc[2*kc][2],   sacc[2*kc][3]);
            af[2] = packbf(sacc[2*kc+1][0], sacc[2*kc+1][1]);
            af[3] = packbf(sacc[2*kc+1][2], sacc[2*kc+1][3]);
            #pragma unroll
            for (int df = 0; df < 8; df++) {
                uint32_t bf2[2];
                bf2[0] = Vs[kc * 8 + tg][df * 8 + g];
                bf2[1] = Vs[kc * 8 + 4 + tg][df * 8 + g];
                mma_bf16(oacc[df], af, bf2);
            }
        }
    }

    float rm = g_rmask[bh];
    float inv0 = rm / l0, inv1 = rm / l1;
    #pragma unroll
    for (int df = 0; df < 8; df++) {
        int dkp = df * 4 + tg;   // pair index: cols df*8+2tg, +1
        g_ctxp[(size_t)(b * SS + row0g) * (DD/2) + h * 32 + dkp] = packbf(oacc[df][0] * inv0, oacc[df][1] * inv0);
        g_ctxp[(size_t)(b * SS + row1g) * (DD/2) + h * 32 + dkp] = packbf(oacc[df][2] * inv1, oacc[df][3] * inv1);
    }
}

// row 0 of each (b,h): uniform attention over all 512 keys -> mean(V) * rmask
__global__ void row0_fix(const float* __restrict__ vl) {
    int bh = blockIdx.x; int b = bh >> 3, h = bh & 7;
    __shared__ float red[256];
    __shared__ float outv[64];
    int tid = threadIdx.x;
    int dk = tid & 63, chunk = tid >> 6;     // 4 chunks x 128 rows
    float s = 0.0f;
    for (int j = chunk * 128; j < chunk * 128 + 128; j++)
        s += vl[(size_t)(b * SS + j) * DD + h * DKH + dk];
    red[tid] = s; __syncthreads();
    if (tid < 64)
        outv[tid] = (red[tid] + red[tid + 64] + red[tid + 128] + red[tid + 192])
                    * (1.0f / 512.0f) * g_rmask[bh];
    __syncthreads();
    if (tid < 32)
        g_ctxp[(size_t)(b * SS) * (DD/2) + h * 32 + tid] = packbf(outv[2 * tid], outv[2 * tid + 1]);
}

// ------------------------- router -------------------------
__global__ void router_kernel(const float* __restrict__ Wg) {
    int warp = (blockIdx.x * blockDim.x + threadIdx.x) >> 5;
    int lane = threadIdx.x & 31;
    if (warp >= NTOK) return;
    const float* xrow = g_ql + (size_t)warp * DD;
    float acc[HR];
    #pragma unroll
    for (int o = 0; o < HR; o++) acc[o] = 0.0f;
    #pragma unroll 4
    for (int c = 0; c < 16; c++) {
        int k = c * 32 + lane;
        float a = xrow[k];
        #pragma unroll
        for (int o = 0; o < HR; o++) acc[o] += a * Wg[k * HR + o];
    }
    #pragma unroll
    for (int o = 0; o < HR; o++)
        #pragma unroll
        for (int off = 16; off; off >>= 1)
            acc[o] += __shfl_xor_sync(0xffffffffu, acc[o], off);
    float mx = acc[0];
    #pragma unroll
    for (int o = 1; o < HR; o++) mx = fmaxf(mx, acc[o]);
    float g[HR], s = 0.0f;
    #pragma unroll
    for (int o = 0; o < HR; o++) { g[o] = expf(acc[o] - mx); s += g[o]; }
    float inv = 1.0f / s;
    #pragma unroll
    for (int o = 0; o < HR; o++) g[o] *= inv;
    int i1 = 0;
    #pragma unroll
    for (int o = 1; o < HR; o++) if (g[o] > g[i1]) i1 = o;
    int i2 = (i1 == 0) ? 1 : 0;
    #pragma unroll
    for (int o = 0; o < HR; o++) if (o != i1 && o != i2 && g[o] > g[i2]) i2 = o;
    if (lane < HR)
        g_dyn[(size_t)warp * HR + lane] = (lane == i1 || lane == i2) ? g[lane] : 0.0f;
}

// ------------------------- rmask -------------------------
__global__ void rmask_kernel() {
    int b = blockIdx.x / HR, o = blockIdx.x % HR;
    __shared__ float red[256];
    int tid = threadIdx.x;
    float s = 0.0f;
    for (int si = tid; si < SS; si += 256)
        s += g_dyn[((size_t)b * SS + si) * HR + o];
    red[tid] = s; __syncthreads();
    for (int st = 128; st; st >>= 1) { if (tid < st) red[tid] += red[tid + st]; __syncthreads(); }
    if (tid == 0) {
        g_rmask[b * HH + 1 + o] = red[0] * (1.0f / SS);
        if (o == 0) g_rmask[b * HH] = 1.0f;
    }
}

// ------------------------- fused residual add + layernorm (+packed mirror) -------------------------
__global__ __launch_bounds__(256) void add_ln(const float* __restrict__ X, const float* __restrict__ A,
                                              const float* __restrict__ gam, const float* __restrict__ bet,
                                              float* __restrict__ outf, uint32_t* __restrict__ outp) {
    int t = blockIdx.x;
    int tid = threadIdx.x;
    int d0 = 2 * tid, d1 = d0 + 1;
    __shared__ float red[256];
    float v0 = X[(size_t)t*DD + d0] + A[(size_t)t*DD + d0];
    float v1 = X[(size_t)t*DD + d1] + A[(size_t)t*DD + d1];
    red[tid] = v0 + v1; __syncthreads();
    for (int s = 128; s; s >>= 1) { if (tid < s) red[tid] += red[tid + s]; __syncthreads(); }
    float mean = red[0] * (1.0f / DD); __syncthreads();
    float e0 = v0 - mean, e1 = v1 - mean;
    red[tid] = e0 * e0 + e1 * e1; __syncthreads();
    for (int s = 128; s; s >>= 1) { if (tid < s) red[tid] += red[tid + s]; __syncthreads(); }
    float inv = rsqrtf(red[0] * (1.0f / DD) + 1e-5f);
    float o0 = e0 * inv * gam[d0] + bet[d0];
    float o1 = e1 * inv * gam[d1] + bet[d1];
    outf[(size_t)t*DD + d0] = o0;
    outf[(size_t)t*DD + d1] = o1;
    outp[(size_t)t*(DD/2) + tid] = packbf(o0, o1);
}

// ------------------------- output-head helpers -------------------------
__global__ void concat_kernel() {
    int t = blockIdx.x, tid = threadIdx.x;   // blockDim = 256
    g_hcatp[(size_t)t * DD + tid]            = g_xp[(size_t)t * (DD/2) + tid];
    g_hcatp[(size_t)t * DD + (DD/2) + tid]   = g_qembp[(size_t)t * (DD/2) + tid];
}

__global__ void final_kernel(const float* __restrict__ ow3, const float* __restrict__ ob3,
                             float* __restrict__ out) {
    int warp = (blockIdx.x * blockDim.x + threadIdx.x) >> 5;
    int lane = threadIdx.x & 31;
    if (warp >= NTOK) return;
    float s = 0.0f;
    #pragma unroll
    for (int c = 0; c < 8; c++) {
        int k = c * 32 + lane;
        s += g_h2[(size_t)warp * FC2D + k] * ow3[k];
    }
    #pragma unroll
    for (int off = 16; off; off >>= 1) s += __shfl_xor_sync(0xffffffffu, s, off);
    if (lane == 0) {
        float z = s + ob3[0];
        out[warp] = 1.0f / (1.0f + expf(-z));
    }
}

// ------------------------- host orchestration -------------------------
struct DP {
    float *x, *y, *ql, *vl, *att, *x1, *h2;
    uint32_t *xp, *yp, *qlp, *x1p, *ctxp, *ffp, *hcatp, *h1p;
    uint32_t *Wqp, *Wvp, *Wop, *W1p, *W2p, *ow1p, *ow2p;
};

static void run_block(const DP& P, float* xqf, uint32_t* xqp, const uint32_t* xvp,
                      int strict, int layer,
                      const float* bq, const float* bv, const float* Wg, const float* bo,
                      const float* ln1g, const float* ln1b,
                      const float* b1, const float* b2,
                      const float* ln2g, const float* ln2b) {
    const uint32_t* wqp = P.Wqp + (size_t)layer * (DD/2) * DD;
    const uint32_t* wvp = P.Wvp + (size_t)layer * (DD/2) * DD;
    const uint32_t* wop = P.Wop + (size_t)layer * (DD/2) * DD;
    const uint32_t* w1p = P.W1p + (size_t)layer * (DD/2) * DFF;
    const uint32_t* w2p = P.W2p + (size_t)layer * (DFF/2) * DD;
    const float* wg  = Wg + (size_t)layer * DD * HR;
    const float* pbq = bq + (size_t)layer * DD;
    const float* pbv = bv + (size_t)layer * DD;
    const float* pbo = bo + (size_t)layer * DD;
    const float* pb1 = b1 + (size_t)layer * DFF;
    const float* pb2 = b2 + (size_t)layer * DD;
    const float* g1 = ln1g + (size_t)layer * DD; const float* be1 = ln1b + (size_t)layer * DD;
    const float* g2 = ln2g + (size_t)layer * DD; const float* be2 = ln2b + (size_t)layer * DD;

    dim3 gproj(DD / 128, NTOK / 128);
    gemm_bf16<<<gproj, 256>>>(xqp, wqp, pbq, P.ql, P.qlp, NTOK, DD, DD, 0);
    gemm_bf16<<<gproj, 256>>>(xvp, wvp, pbv, P.vl, nullptr, NTOK, DD, DD, 0);
    router_kernel<<<NTOK / 4, 128>>>(wg);
    rmask_kernel<<<BB * HR, 256>>>();
    flash_attn<<<dim3(SS / 128, BB * HH), 256>>>(P.vl, strict);
    row0_fix<<<BB * HH, 256>>>(P.vl);
    gemm_bf16<<<gproj, 256>>>(P.ctxp, wop, pbo, P.att, nullptr, NTOK, DD, DD, 0);
    add_ln<<<NTOK, 256>>>(xqf, P.att, g1, be1, P.x1, P.x1p);
    gemm_bf16<<<dim3(DFF / 128, NTOK / 128), 256>>>(P.x1p, w1p, pb1, nullptr, P.ffp, NTOK, DFF, DD, 1);
    gemm_bf16<<<gproj, 256>>>(P.ffp, w2p, pb2, P.att, nullptr, NTOK, DD, DFF, 0);
    add_ln<<<NTOK, 256>>>(P.x1, P.att, g2, be2, xqf, xqp);
}

extern "C" void kernel_launch(void* const* d_in, const int* in_sizes, int n_in,
                              void* d_out, int out_size) {
    const int*   q_data   = (const int*)d_in[0];
    const int*   target   = (const int*)d_in[1];
    const int*   pid_data = (const int*)d_in[2];
    const float* q_embed  = (const float*)d_in[3];
    const float* qa_embed = (const float*)d_in[4];
    const float* q_diff   = (const float*)d_in[5];
    const float* qa_diff  = (const float*)d_in[6];
    const float* pid_diff = (const float*)d_in[7];
    const float* Wq = (const float*)d_in[8];   const float* bq = (const float*)d_in[9];
    const float* Wv = (const float*)d_in[10];  const float* bv = (const float*)d_in[11];
    const float* Wg = (const float*)d_in[12];
    const float* Wo = (const float*)d_in[13];  const float* bo = (const float*)d_in[14];
    const float* ln1g = (const float*)d_in[15]; const float* ln1b = (const float*)d_in[16];
    const float* W1 = (const float*)d_in[17];  const float* b1 = (const float*)d_in[18];
    const float* W2 = (const float*)d_in[19];  const float* b2 = (const float*)d_in[20];
    const float* ln2g = (const float*)d_in[21]; const float* ln2b = (const float*)d_in[22];
    const float* ow1 = (const float*)d_in[23]; const float* ob1 = (const float*)d_in[24];
    const float* ow2 = (const float*)d_in[25]; const float* ob2 = (const float*)d_in[26];
    const float* ow3 = (const float*)d_in[27]; const float* ob3 = (const float*)d_in[28];
    float* out = (float*)d_out;

    DP P; void* p;
    cudaGetSymbolAddress(&p, g_x);     P.x   = (float*)p;
    cudaGetSymbolAddress(&p, g_y);     P.y   = (float*)p;
    cudaGetSymbolAddress(&p, g_ql);    P.ql  = (float*)p;
    cudaGetSymbolAddress(&p, g_vl);    P.vl  = (float*)p;
    cudaGetSymbolAddress(&p, g_att);   P.att = (float*)p;
    cudaGetSymbolAddress(&p, g_x1);    P.x1  = (float*)p;
    cudaGetSymbolAddress(&p, g_h2);    P.h2  = (float*)p;
    cudaGetSymbolAddress(&p, g_xp);    P.xp   = (uint32_t*)p;
    cudaGetSymbolAddress(&p, g_yp);    P.yp   = (uint32_t*)p;
    cudaGetSymbolAddress(&p, g_qlp);   P.qlp  = (uint32_t*)p;
    cudaGetSymbolAddress(&p, g_x1p);   P.x1p  = (uint32_t*)p;
    cudaGetSymbolAddress(&p, g_ctxp);  P.ctxp = (uint32_t*)p;
    cudaGetSymbolAddress(&p, g_ffp);   P.ffp  = (uint32_t*)p;
    cudaGetSymbolAddress(&p, g_hcatp); P.hcatp= (uint32_t*)p;
    cudaGetSymbolAddress(&p, g_h1p);   P.h1p  = (uint32_t*)p;
    cudaGetSymbolAddress(&p, g_Wqp);   P.Wqp  = (uint32_t*)p;
    cudaGetSymbolAddress(&p, g_Wvp);   P.Wvp  = (uint32_t*)p;
    cudaGetSymbolAddress(&p, g_Wop);   P.Wop  = (uint32_t*)p;
    cudaGetSymbolAddress(&p, g_W1p);   P.W1p  = (uint32_t*)p;
    cudaGetSymbolAddress(&p, g_W2p);   P.W2p  = (uint32_t*)p;
    cudaGetSymbolAddress(&p, g_ow1p);  P.ow1p = (uint32_t*)p;
    cudaGetSymbolAddress(&p, g_ow2p);  P.ow2p = (uint32_t*)p;

    // ---- pack all weights to bf16 (stacked: pairs never cross layer bounds) ----
    {
        int kp, n4;
        kp = 6*DD/2;  n4 = DD/4;
        pack_mat4<<<(int)(((size_t)kp*n4 + 255)/256), 256>>>(Wq, P.Wqp, kp, n4);
        pack_mat4<<<(int)(((size_t)kp*n4 + 255)/256), 256>>>(Wv, P.Wvp, kp, n4);
        pack_mat4<<<(int)(((size_t)kp*n4 + 255)/256), 256>>>(Wo, P.Wop, kp, n4);
        kp = 6*DD/2;  n4 = DFF/4;
        pack_mat4<<<(int)(((size_t)kp*n4 + 255)/256), 256>>>(W1, P.W1p, kp, n4);
        kp = 6*DFF/2; n4 = DD/4;
        pack_mat4<<<(int)(((size_t)kp*n4 + 255)/256), 256>>>(W2, P.W2p, kp, n4);
        kp = DD;      n4 = FC1D/4;   // K = 2D
        pack_mat4<<<(int)(((size_t)kp*n4 + 255)/256), 256>>>(ow1, P.ow1p, kp, n4);
        kp = FC1D/2;  n4 = FC2D/4;
        pack_mat4<<<(int)(((size_t)kp*n4 + 255)/256), 256>>>(ow2, P.ow2p, kp, n4);
    }

    embed_kernel<<<NTOK, 256>>>(q_data, target, pid_data, q_embed, qa_embed,
                                q_diff, qa_diff, pid_diff);

    // blocks_1: y = block(y, y, strict=False), layers 0..1
    run_block(P, P.y, P.yp, P.yp, 0, 0, bq, bv, Wg, bo, ln1g, ln1b, b1, b2, ln2g, ln2b);
    run_block(P, P.y, P.yp, P.yp, 0, 1, bq, bv, Wg, bo, ln1g, ln1b, b1, b2, ln2g, ln2b);
    // blocks_2: alternate self (non-strict) / cross-with-y (strict), layers 2..5
    run_block(P, P.x, P.xp, P.xp, 0, 2, bq, bv, Wg, bo, ln1g, ln1b, b1, b2, ln2g, ln2b);
    run_block(P, P.x, P.xp, P.yp, 1, 3, bq, bv, Wg, bo, ln1g, ln1b, b1, b2, ln2g, ln2b);
    run_block(P, P.x, P.xp, P.xp, 0, 4, bq, bv, Wg, bo, ln1g, ln1b, b1, b2, ln2g, ln2b);
    run_block(P, P.x, P.xp, P.yp, 1, 5, bq, bv, Wg, bo, ln1g, ln1b, b1, b2, ln2g, ln2b);

    // output head
    concat_kernel<<<NTOK, 256>>>();
    gemm_bf16<<<dim3(FC1D / 128, NTOK / 128), 256>>>(P.hcatp, P.ow1p, ob1, nullptr, P.h1p, NTOK, FC1D, 2*DD, 1);
    gemm_bf16<<<dim3(FC2D / 128, NTOK / 128), 256>>>(P.h1p, P.ow2p, ob2, P.h2, nullptr, NTOK, FC2D, FC1D, 1);
    final_kernel<<<NTOK / 4, 128>>>(ow3, ob3, out);
}

// round 16
// speedup vs baseline: 1.0015x; 1.0015x over previous
#include <cuda_runtime.h>
#include <math.h>
#include <stdint.h>

#define BB 24
#define SS 512
#define DD 512
#define HH 8
#define DKH 64
#define DFF 2048
#define FC1D 512
#define FC2D 256
#define NTOK (BB*SS)
#define HR 7   /* H - HS routed heads */

// ------------------------- scratch (device globals) -------------------------
__device__ __align__(16) float g_x[NTOK*DD];
__device__ __align__(16) float g_y[NTOK*DD];
__device__ __align__(16) float g_ql[NTOK*DD];
__device__ __align__(16) float g_vl[NTOK*DD];
__device__ __align__(16) float g_att[NTOK*DD];
__device__ __align__(16) float g_x1[NTOK*DD];
__device__ __align__(16) float g_h2[NTOK*FC2D];
__device__ float g_dyn[NTOK*HR];
__device__ float g_rmask[BB*HH];

// packed bf16 mirrors (u32 = pair of bf16 along the consumer-K dim)
__device__ __align__(16) uint32_t g_xp[NTOK*DD/2];
__device__ __align__(16) uint32_t g_yp[NTOK*DD/2];
__device__ __align__(16) uint32_t g_qembp[NTOK*DD/2];
__device__ __align__(16) uint32_t g_qlp[NTOK*DD/2];
__device__ __align__(16) uint32_t g_ctxp[NTOK*DD/2];
__device__ __align__(16) uint32_t g_x1p[NTOK*DD/2];
__device__ __align__(16) uint32_t g_ffp[NTOK*DFF/2];
__device__ __align__(16) uint32_t g_hcatp[NTOK*DD];      // 2D/2 = D u32 per row
__device__ __align__(16) uint32_t g_h1p[NTOK*FC1D/2];

// packed weights
__device__ __align__(16) uint32_t g_Wqp[6*(DD/2)*DD];
__device__ __align__(16) uint32_t g_Wvp[6*(DD/2)*DD];
__device__ __align__(16) uint32_t g_Wop[6*(DD/2)*DD];
__device__ __align__(16) uint32_t g_W1p[6*(DD/2)*DFF];
__device__ __align__(16) uint32_t g_W2p[6*(DFF/2)*DD];
__device__ __align__(16) uint32_t g_ow1p[DD*FC1D];
__device__ __align__(16) uint32_t g_ow2p[(FC1D/2)*FC2D];

// ------------------------- helpers -------------------------
__device__ __forceinline__ uint32_t packbf(float lo, float hi) {
    uint32_t r;
    asm("cvt.rn.bf16x2.f32 %0, %1, %2;" : "=r"(r) : "f"(hi), "f"(lo));  // first src -> high half
    return r;
}

__device__ __forceinline__ void mma_bf16(float c[4], const uint32_t a[4], const uint32_t b[2]) {
    asm volatile(
        "mma.sync.aligned.m16n8k16.row.col.f32.bf16.bf16.f32 "
        "{%0,%1,%2,%3}, {%4,%5,%6,%7}, {%8,%9}, {%0,%1,%2,%3};"
        : "+f"(c[0]), "+f"(c[1]), "+f"(c[2]), "+f"(c[3])
        : "r"(a[0]), "r"(a[1]), "r"(a[2]), "r"(a[3]), "r"(b[0]), "r"(b[1]));
}

__device__ __forceinline__ void cp16(void* dst, const void* src) {
    uint32_t d = (uint32_t)__cvta_generic_to_shared(dst);
    asm volatile("cp.async.cg.shared.global [%0], [%1], 16;" :: "r"(d), "l"(src));
}

// ------------------------- vectorized weight packing -------------------------
// W[K][N] f32 -> out[K/2][N] u32 ; pairs along K. Works on layer-stacked weights
// because per-layer K is even, so pairs never cross layer boundaries.
__global__ void pack_mat4(const float* __restrict__ W, uint32_t* __restrict__ out,
                          int KP, int N4) {
    size_t idx = (size_t)blockIdx.x * 256 + threadIdx.x;
    if (idx >= (size_t)KP * N4) return;
    int n4 = (int)(idx % N4);
    size_t kp = idx / N4;
    int N = N4 * 4;
    float4 r0 = *(const float4*)&W[(2 * kp) * N + (size_t)n4 * 4];
    float4 r1 = *(const float4*)&W[(2 * kp + 1) * N + (size_t)n4 * 4];
    uint4 o;
    o.x = packbf(r0.x, r1.x);
    o.y = packbf(r0.y, r1.y);
    o.z = packbf(r0.z, r1.z);
    o.w = packbf(r0.w, r1.w);
    ((uint4*)out)[idx] = o;
}

// ------------------------- embeddings -------------------------
__global__ void embed_kernel(const int* __restrict__ qd, const int* __restrict__ tg,
                             const int* __restrict__ pid,
                             const float* __restrict__ qtab, const float* __restrict__ qatab,
                             const float* __restrict__ qdtab, const float* __restrict__ qadtab,
                             const float* __restrict__ pdtab) {
    int t = blockIdx.x;
    int tid = threadIdx.x;              // blockDim = 256
    int d0 = 2 * tid, d1 = d0 + 1;
    int qi = qd[t], ti = tg[t], pi = pid[t];
    float ps = pdtab[pi];
    float qe0 = qtab[(size_t)qi*DD + d0], qe1 = qtab[(size_t)qi*DD + d1];
    float qv0 = qdtab[(size_t)qi*DD + d0], qv1 = qdtab[(size_t)qi*DD + d1];
    float em0 = qe0 + ps * qv0, em1 = qe1 + ps * qv1;
    float qa0 = qatab[(size_t)ti*DD + d0] + qe0 + ps * (qadtab[(size_t)ti*DD + d0] + qv0);
    float qa1 = qatab[(size_t)ti*DD + d1] + qe1 + ps * (qadtab[(size_t)ti*DD + d1] + qv1);
    g_x[(size_t)t*DD + d0] = em0; g_x[(size_t)t*DD + d1] = em1;
    g_y[(size_t)t*DD + d0] = qa0; g_y[(size_t)t*DD + d1] = qa1;
    g_xp[(size_t)t*(DD/2) + tid]    = packbf(em0, em1);
    g_yp[(size_t)t*(DD/2) + tid]    = packbf(qa0, qa1);
    g_qembp[(size_t)t*(DD/2) + tid] = packbf(em0, em1);
}

// ------------------------- bf16 tensor-core GEMM, 2-stage cp.async pipeline -------------------------
__global__ __launch_bounds__(256) void gemm_bf16(const uint32_t* __restrict__ Apk,
                                                 const uint32_t* __restrict__ Bpk,
                                                 const float* __restrict__ bias,
                                                 float* __restrict__ C, uint32_t* __restrict__ Cpk,
                                                 int M, int N, int K, int relu) {
    __shared__ uint32_t As[2][128][20];
    __shared__ uint32_t Bs[2][16][136];
    int tid = threadIdx.x;
    int lane = tid & 31, warp = tid >> 5;
    int wm = warp >> 1, wn = warp & 1;
    int g = lane >> 2, tg = lane & 3;
    int m0 = blockIdx.y * 128, n0 = blockIdx.x * 128;
    int KP = K >> 1;
    int NK = K >> 5;

    float acc[2][8][4];
    #pragma unroll
    for (int i = 0; i < 2; i++)
        #pragma unroll
        for (int j = 0; j < 8; j++)
            #pragma unroll
            for (int r = 0; r < 4; r++) acc[i][j][r] = 0.0f;

#define LOAD_TILES(st, it) do {                                                   \
    int base = (it) * 16;                                                         \
    _Pragma("unroll")                                                             \
    for (int p = 0; p < 2; p++) {                                                 \
        int id = tid + p * 256; int r = id >> 2; int c4 = (id & 3) * 4;           \
        cp16(&As[st][r][c4], &Apk[(size_t)(m0 + r) * KP + base + c4]);            \
    }                                                                             \
    _Pragma("unroll")                                                             \
    for (int p = 0; p < 2; p++) {                                                 \
        int id = tid + p * 256; int r = id >> 5; int c4 = (id & 31) * 4;          \
        cp16(&Bs[st][r][c4], &Bpk[(size_t)(base + r) * N + n0 + c4]);             \
    }                                                                             \
    asm volatile("cp.async.commit_group;");                                       \
} while (0)

    LOAD_TILES(0, 0);
    int s = 0;
    for (int it = 0; it < NK; it++) {
        if (it + 1 < NK) {
            LOAD_TILES(s ^ 1, it + 1);
            asm volatile("cp.async.wait_group 1;");
        } else {
            asm volatile("cp.async.wait_group 0;");
        }
        __syncthreads();
        #pragma unroll
        for (int kk = 0; kk < 2; kk++) {
            int kb = kk * 8;
            uint32_t af[2][4], bf[8][2];
            #pragma unroll
            for (int i = 0; i < 2; i++) {
                int m = wm * 32 + i * 16;
                af[i][0] = As[s][m + g][kb + tg];
                af[i][1] = As[s][m + 8 + g][kb + tg];
                af[i][2] = As[s][m + g][kb + 4 + tg];
                af[i][3] = As[s][m + 8 + g][kb + 4 + tg];
            }
            #pragma unroll
            for (int j = 0; j < 8; j++) {
                int n = wn * 64 + j * 8 + g;
                bf[j][0] = Bs[s][kb + tg][n];
                bf[j][1] = Bs[s][kb + 4 + tg][n];
            }
            #pragma unroll
            for (int i = 0; i < 2; i++)
                #pragma unroll
                for (int j = 0; j < 8; j++)
                    mma_bf16(acc[i][j], af[i], bf[j]);
        }
        __syncthreads();
        s ^= 1;
    }
#undef LOAD_TILES

    #pragma unroll
    for (int i = 0; i < 2; i++) {
        int m = m0 + wm * 32 + i * 16 + g;
        #pragma unroll
        for (int j = 0; j < 8; j++) {
            int n = n0 + wn * 64 + j * 8 + tg * 2;
            float b0 = bias[n], b1 = bias[n + 1];
            float v0 = acc[i][j][0] + b0, v1 = acc[i][j][1] + b1;
            float v2 = acc[i][j][2] + b0, v3 = acc[i][j][3] + b1;
            if (relu) { v0 = fmaxf(v0, 0.f); v1 = fmaxf(v1, 0.f); v2 = fmaxf(v2, 0.f); v3 = fmaxf(v3, 0.f); }
            if (C) {
                C[(size_t)m * N + n]           = v0;
                C[(size_t)m * N + n + 1]       = v1;
                C[(size_t)(m + 8) * N + n]     = v2;
                C[(size_t)(m + 8) * N + n + 1] = v3;
            }
            if (Cpk) {
                Cpk[(size_t)m * (N >> 1) + (n >> 1)]       = packbf(v0, v1);
                Cpk[(size_t)(m + 8) * (N >> 1) + (n >> 1)] = packbf(v2, v3);
            }
        }
    }
}

// ------------------------- fused flash attention -------------------------
// One CTA = 128 query rows of one (b,h). 8 warps x 16 rows. Online softmax.
// K == Q (kq_same). Causal early-exit over 64-wide j-tiles. Writes g_ctxp packed.
// Token-row-0 (uniform softmax) is overwritten afterwards by row0_fix.
__global__ __launch_bounds__(256) void flash_attn(const float* __restrict__ vl, int strict) {
    int bh = blockIdx.y; int b = bh >> 3, h = bh & 7;
    int i0 = blockIdx.x * 128;
    __shared__ uint32_t Qs[128][36];   // [row][dkpair]
    __shared__ uint32_t Ks[64][36];    // [row][dkpair]  (same layout as Qs)
    __shared__ uint32_t Vs[32][72];    // [jpair][dk]
    int tid = threadIdx.x, lane = tid & 31, w = tid >> 5;
    int g = lane >> 2, tg = lane & 3;

    // load Q tile (coalesced, conflict-free)
    #pragma unroll
    for (int p = 0; p < 16; p++) {
        int id = tid + p * 256;
        int r = id >> 5, c = id & 31;
        Qs[r][c] = g_qlp[(size_t)(b * SS + i0 + r) * (DD/2) + h * 32 + c];
    }

    float oacc[8][4];
    #pragma unroll
    for (int d = 0; d < 8; d++)
        #pragma unroll
        for (int r = 0; r < 4; r++) oacc[d][r] = 0.0f;
    float m0 = -1e30f, m1 = -1e30f, l0 = 0.0f, l1 = 0.0f;

    int row0g = i0 + w * 16 + g;   // global seq row for c0/c1 of fragments
    int row1g = row0g + 8;

    int njt = 2 * blockIdx.x + 2;  // causal tile limit: j0 <= i0+127

    for (int jt = 0; jt < njt; jt++) {
        int j0 = jt * 64;
        __syncthreads();           // previous iter's K/V fully consumed
        // K tile: 64 rows x 32 dkpairs
        #pragma unroll
        for (int p = 0; p < 8; p++) {
            int id = tid + p * 256;
            int r = id >> 5, c = id & 31;
            Ks[r][c] = g_qlp[(size_t)(b * SS + j0 + r) * (DD/2) + h * 32 + c];
        }
        // V tile: pack fp32 rows pairs -> Vs[jpair][dk]
        #pragma unroll
        for (int p = 0; p < 2; p++) {
            int id = tid + p * 256;
            int jp = id >> 4, c = (id & 15) * 4;
            const float* v0p = &vl[(size_t)(b * SS + j0 + 2 * jp) * DD + h * DKH + c];
            const float* v1p = v0p + DD;
            float4 a = *(const float4*)v0p;
            float4 bb = *(const float4*)v1p;
            Vs[jp][c + 0] = packbf(a.x, bb.x);
            Vs[jp][c + 1] = packbf(a.y, bb.y);
            Vs[jp][c + 2] = packbf(a.z, bb.z);
            Vs[jp][c + 3] = packbf(a.w, bb.w);
        }
        __syncthreads();

        // ---- scores: S[16x64] per warp ----
        float sacc[8][4];
        #pragma unroll
        for (int jf = 0; jf < 8; jf++)
            #pragma unroll
            for (int r = 0; r < 4; r++) sacc[jf][r] = 0.0f;
        #pragma unroll
        for (int kc = 0; kc < 4; kc++) {
            uint32_t af[4];
            af[0] = Qs[w * 16 + g][kc * 8 + tg];
            af[1] = Qs[w * 16 + 8 + g][kc * 8 + tg];
            af[2] = Qs[w * 16 + g][kc * 8 + 4 + tg];
            af[3] = Qs[w * 16 + 8 + g][kc * 8 + 4 + tg];
            #pragma unroll
            for (int jf = 0; jf < 8; jf++) {
                uint32_t bf2[2];
                bf2[0] = Ks[jf * 8 + g][kc * 8 + tg];
                bf2[1] = Ks[jf * 8 + g][kc * 8 + 4 + tg];
                mma_bf16(sacc[jf], af, bf2);
            }
        }

        // ---- mask + scale, tile row-max ----
        float tm0 = -1e30f, tm1 = -1e30f;
        #pragma unroll
        for (int jf = 0; jf < 8; jf++) {
            int c0 = j0 + jf * 8 + 2 * tg;
            int c1 = c0 + 1;
            bool a00 = strict ? (c0 < row0g || (row0g == 0 && c0 == 0)) : (c0 <= row0g);
            bool a01 = strict ? (c1 < row0g) : (c1 <= row0g);
            bool a10 = strict ? (c0 < row1g) : (c0 <= row1g);
            bool a11 = strict ? (c1 < row1g) : (c1 <= row1g);
            sacc[jf][0] = a00 ? sacc[jf][0] * 0.125f : -1e30f;
            sacc[jf][1] = a01 ? sacc[jf][1] * 0.125f : -1e30f;
            sacc[jf][2] = a10 ? sacc[jf][2] * 0.125f : -1e30f;
            sacc[jf][3] = a11 ? sacc[jf][3] * 0.125f : -1e30f;
            tm0 = fmaxf(tm0, fmaxf(sacc[jf][0], sacc[jf][1]));
            tm1 = fmaxf(tm1, fmaxf(sacc[jf][2], sacc[jf][3]));
        }
        tm0 = fmaxf(tm0, __shfl_xor_sync(0xffffffffu, tm0, 1));
        tm0 = fmaxf(tm0, __shfl_xor_sync(0xffffffffu, tm0, 2));
        tm1 = fmaxf(tm1, __shfl_xor_sync(0xffffffffu, tm1, 1));
        tm1 = fmaxf(tm1, __shfl_xor_sync(0xffffffffu, tm1, 2));

        float nm0 = fmaxf(m0, tm0), nm1 = fmaxf(m1, tm1);
        float sc0 = expf(m0 - nm0), sc1 = expf(m1 - nm1);
        float ts0 = 0.0f, ts1 = 0.0f;
        #pragma unroll
        for (int jf = 0; jf < 8; jf++) {
            float p0 = expf(sacc[jf][0] - nm0);
            float p1 = expf(sacc[jf][1] - nm0);
            float p2 = expf(sacc[jf][2] - nm1);
            float p3 = expf(sacc[jf][3] - nm1);
            sacc[jf][0] = p0; sacc[jf][1] = p1; sacc[jf][2] = p2; sacc[jf][3] = p3;
            ts0 += p0 + p1; ts1 += p2 + p3;
        }
        ts0 += __shfl_xor_sync(0xffffffffu, ts0, 1);
        ts0 += __shfl_xor_sync(0xffffffffu, ts0, 2);
        ts1 += __shfl_xor_sync(0xffffffffu, ts1, 1);
        ts1 += __shfl_xor_sync(0xffffffffu, ts1, 2);
        l0 = l0 * sc0 + ts0;
        l1 = l1 * sc1 + ts1;
        m0 = nm0; m1 = nm1;
        #pragma unroll
        for (int d = 0; d < 8; d++) {
            oacc[d][0] *= sc0; oacc[d][1] *= sc0;
            oacc[d][2] *= sc1; oacc[d][3] *= sc1;
        }

        // ---- P @ V: C-frag of scores re-packed as A-frag ----
        #pragma unroll
        for (int kc = 0; kc < 4; kc++) {
            uint32_t af[4];
            af[0] = packbf(sacc[2*kc][0],   sacc[2*kc][1]);
            af[1] = packbf(sacc[2*kc][2],   sacc[2*kc][3]);
            af[2] = packbf(sacc[2*kc+1][0], sacc[2*kc+1][1]);
            af[3] = packbf(sacc[2*kc+1][2], sacc[2*kc+1][3]);
            #pragma unroll
            for (int df = 0; df < 8; df++) {
                uint32_t bf2[2];
                bf2[0] = Vs[kc * 8 + tg][df * 8 + g];
                bf2[1] = Vs[kc * 8 + 4 + tg][df * 8 + g];
                mma_bf16(oacc[df], af, bf2);
            }
        }
    }

    float rm = g_rmask[bh];
    float inv0 = rm / l0, inv1 = rm / l1;
    #pragma unroll
    for (int df = 0; df < 8; df++) {
        int dkp = df * 4 + tg;   // pair index: cols df*8+2tg, +1
        g_ctxp[(size_t)(b * SS + row0g) * (DD/2) + h * 32 + dkp] = packbf(oacc[df][0] * inv0, oacc[df][1] * inv0);
        g_ctxp[(size_t)(b * SS + row1g) * (DD/2) + h * 32 + dkp] = packbf(oacc[df][2] * inv1, oacc[df][3] * inv1);
    }
}

// row 0 of each (b,h): uniform attention over all 512 keys -> mean(V) * rmask
__global__ void row0_fix(const float* __restrict__ vl) {
    int bh = blockIdx.x; int b = bh >> 3, h = bh & 7;
    __shared__ float red[256];
    __shared__ float outv[64];
    int tid = threadIdx.x;
    int dk = tid & 63, chunk = tid >> 6;     // 4 chunks x 128 rows
    float s = 0.0f;
    for (int j = chunk * 128; j < chunk * 128 + 128; j++)
        s += vl[(size_t)(b * SS + j) * DD + h * DKH + dk];
    red[tid] = s; __syncthreads();
    if (tid < 64)
        outv[tid] = (red[tid] + red[tid + 64] + red[tid + 128] + red[tid + 192])
                    * (1.0f / 512.0f) * g_rmask[bh];
    __syncthreads();
    if (tid < 32)
        g_ctxp[(size_t)(b * SS) * (DD/2) + h * 32 + tid] = packbf(outv[2 * tid], outv[2 * tid + 1]);
}

// ------------------------- router -------------------------
__global__ void router_kernel(const float* __restrict__ Wg) {
    int warp = (blockIdx.x * blockDim.x + threadIdx.x) >> 5;
    int lane = threadIdx.x & 31;
    if (warp >= NTOK) return;
    const float* xrow = g_ql + (size_t)warp * DD;
    float acc[HR];
    #pragma unroll
    for (int o = 0; o < HR; o++) acc[o] = 0.0f;
    #pragma unroll 4
    for (int c = 0; c < 16; c++) {
        int k = c * 32 + lane;
        float a = xrow[k];
        #pragma unroll
        for (int o = 0; o < HR; o++) acc[o] += a * Wg[k * HR + o];
    }
    #pragma unroll
    for (int o = 0; o < HR; o++)
        #pragma unroll
        for (int off = 16; off; off >>= 1)
            acc[o] += __shfl_xor_sync(0xffffffffu, acc[o], off);
    float mx = acc[0];
    #pragma unroll
    for (int o = 1; o < HR; o++) mx = fmaxf(mx, acc[o]);
    float g[HR], s = 0.0f;
    #pragma unroll
    for (int o = 0; o < HR; o++) { g[o] = expf(acc[o] - mx); s += g[o]; }
    float inv = 1.0f / s;
    #pragma unroll
    for (int o = 0; o < HR; o++) g[o] *= inv;
    int i1 = 0;
    #pragma unroll
    for (int o = 1; o < HR; o++) if (g[o] > g[i1]) i1 = o;
    int i2 = (i1 == 0) ? 1 : 0;
    #pragma unroll
    for (int o = 0; o < HR; o++) if (o != i1 && o != i2 && g[o] > g[i2]) i2 = o;
    if (lane < HR)
        g_dyn[(size_t)warp * HR + lane] = (lane == i1 || lane == i2) ? g[lane] : 0.0f;
}

// ------------------------- rmask -------------------------
__global__ void rmask_kernel() {
    int b = blockIdx.x / HR, o = blockIdx.x % HR;
    __shared__ float red[256];
    int tid = threadIdx.x;
    float s = 0.0f;
    for (int si = tid; si < SS; si += 256)
        s += g_dyn[((size_t)b * SS + si) * HR + o];
    red[tid] = s; __syncthreads();
    for (int st = 128; st; st >>= 1) { if (tid < st) red[tid] += red[tid + st]; __syncthreads(); }
    if (tid == 0) {
        g_rmask[b * HH + 1 + o] = red[0] * (1.0f / SS);
        if (o == 0) g_rmask[b * HH] = 1.0f;
    }
}

// ------------------------- fused residual add + layernorm (+packed mirror) -------------------------
__global__ __launch_bounds__(256) void add_ln(const float* __restrict__ X, const float* __restrict__ A,
                                              const float* __restrict__ gam, const float* __restrict__ bet,
                                              float* __restrict__ outf, uint32_t* __restrict__ outp) {
    int t = blockIdx.x;
    int tid = threadIdx.x;
    int d0 = 2 * tid, d1 = d0 + 1;
    __shared__ float red[256];
    float v0 = X[(size_t)t*DD + d0] + A[(size_t)t*DD + d0];
    float v1 = X[(size_t)t*DD + d1] + A[(size_t)t*DD + d1];
    red[tid] = v0 + v1; __syncthreads();
    for (int s = 128; s; s >>= 1) { if (tid < s) red[tid] += red[tid + s]; __syncthreads(); }
    float mean = red[0] * (1.0f / DD); __syncthreads();
    float e0 = v0 - mean, e1 = v1 - mean;
    red[tid] = e0 * e0 + e1 * e1; __syncthreads();
    for (int s = 128; s; s >>= 1) { if (tid < s) red[tid] += red[tid + s]; __syncthreads(); }
    float inv = rsqrtf(red[0] * (1.0f / DD) + 1e-5f);
    float o0 = e0 * inv * gam[d0] + bet[d0];
    float o1 = e1 * inv * gam[d1] + bet[d1];
    outf[(size_t)t*DD + d0] = o0;
    outf[(size_t)t*DD + d1] = o1;
    outp[(size_t)t*(DD/2) + tid] = packbf(o0, o1);
}

// ------------------------- output-head helpers -------------------------
__global__ void concat_kernel() {
    int t = blockIdx.x, tid = threadIdx.x;   // blockDim = 256
    g_hcatp[(size_t)t * DD + tid]            = g_xp[(size_t)t * (DD/2) + tid];
    g_hcatp[(size_t)t * DD + (DD/2) + tid]   = g_qembp[(size_t)t * (DD/2) + tid];
}

__global__ void final_kernel(const float* __restrict__ ow3, const float* __restrict__ ob3,
                             float* __restrict__ out) {
    int warp = (blockIdx.x * blockDim.x + threadIdx.x) >> 5;
    int lane = threadIdx.x & 31;
    if (warp >= NTOK) return;
    float s = 0.0f;
    #pragma unroll
    for (int c = 0; c < 8; c++) {
        int k = c * 32 + lane;
        s += g_h2[(size_t)warp * FC2D + k] * ow3[k];
    }
    #pragma unroll
    for (int off = 16; off; off >>= 1) s += __shfl_xor_sync(0xffffffffu, s, off);
    if (lane == 0) {
        float z = s + ob3[0];
        out[warp] = 1.0f / (1.0f + expf(-z));
    }
}

// ------------------------- host orchestration -------------------------
struct DP {
    float *x, *y, *ql, *vl, *att, *x1, *h2;
    uint32_t *xp, *yp, *qlp, *x1p, *ctxp, *ffp, *hcatp, *h1p;
    uint32_t *Wqp, *Wvp, *Wop, *W1p, *W2p, *ow1p, *ow2p;
};

static void run_block(const DP& P, float* xqf, uint32_t* xqp, const uint32_t* xvp,
                      int strict, int layer,
                      const float* bq, const float* bv, const float* Wg, const float* bo,
                      const float* ln1g, const float* ln1b,
                      const float* b1, const float* b2,
                      const float* ln2g, const float* ln2b) {
    const uint32_t* wqp = P.Wqp + (size_t)layer * (DD/2) * DD;
    const uint32_t* wvp = P.Wvp + (size_t)layer * (DD/2) * DD;
    const uint32_t* wop = P.Wop + (size_t)layer * (DD/2) * DD;
    const uint32_t* w1p = P.W1p + (size_t)layer * (DD/2) * DFF;
    const uint32_t* w2p = P.W2p + (size_t)layer * (DFF/2) * DD;
    const float* wg  = Wg + (size_t)layer * DD * HR;
    const float* pbq = bq + (size_t)layer * DD;
    const float* pbv = bv + (size_t)layer * DD;
    const float* pbo = bo + (size_t)layer * DD;
    const float* pb1 = b1 + (size_t)layer * DFF;
    const float* pb2 = b2 + (size_t)layer * DD;
    const float* g1 = ln1g + (size_t)layer * DD; const float* be1 = ln1b + (size_t)layer * DD;
    const float* g2 = ln2g + (size_t)layer * DD; const float* be2 = ln2b + (size_t)layer * DD;

    dim3 gproj(DD / 128, NTOK / 128);
    gemm_bf16<<<gproj, 256>>>(xqp, wqp, pbq, P.ql, P.qlp, NTOK, DD, DD, 0);
    gemm_bf16<<<gproj, 256>>>(xvp, wvp, pbv, P.vl, nullptr, NTOK, DD, DD, 0);
    router_kernel<<<NTOK / 4, 128>>>(wg);
    rmask_kernel<<<BB * HR, 256>>>();
    flash_attn<<<dim3(SS / 128, BB * HH), 256>>>(P.vl, strict);
    row0_fix<<<BB * HH, 256>>>(P.vl);
    gemm_bf16<<<gproj, 256>>>(P.ctxp, wop, pbo, P.att, nullptr, NTOK, DD, DD, 0);
    add_ln<<<NTOK, 256>>>(xqf, P.att, g1, be1, P.x1, P.x1p);
    gemm_bf16<<<dim3(DFF / 128, NTOK / 128), 256>>>(P.x1p, w1p, pb1, nullptr, P.ffp, NTOK, DFF, DD, 1);
    gemm_bf16<<<gproj, 256>>>(P.ffp, w2p, pb2, P.att, nullptr, NTOK, DD, DFF, 0);
    add_ln<<<NTOK, 256>>>(P.x1, P.att, g2, be2, xqf, xqp);
}

extern "C" void kernel_launch(void* const* d_in, const int* in_sizes, int n_in,
                              void* d_out, int out_size) {
    const int*   q_data   = (const int*)d_in[0];
    const int*   target   = (const int*)d_in[1];
    const int*   pid_data = (const int*)d_in[2];
    const float* q_embed  = (const float*)d_in[3];
    const float* qa_embed = (const float*)d_in[4];
    const float* q_diff   = (const float*)d_in[5];
    const float* qa_diff  = (const float*)d_in[6];
    const float* pid_diff = (const float*)d_in[7];
    const float* Wq = (const float*)d_in[8];   const float* bq = (const float*)d_in[9];
    const float* Wv = (const float*)d_in[10];  const float* bv = (const float*)d_in[11];
    const float* Wg = (const float*)d_in[12];
    const float* Wo = (const float*)d_in[13];  const float* bo = (const float*)d_in[14];
    const float* ln1g = (const float*)d_in[15]; const float* ln1b = (const float*)d_in[16];
    const float* W1 = (const float*)d_in[17];  const float* b1 = (const float*)d_in[18];
    const float* W2 = (const float*)d_in[19];  const float* b2 = (const float*)d_in[20];
    const float* ln2g = (const float*)d_in[21]; const float* ln2b = (const float*)d_in[22];
    const float* ow1 = (const float*)d_in[23]; const float* ob1 = (const float*)d_in[24];
    const float* ow2 = (const float*)d_in[25]; const float* ob2 = (const float*)d_in[26];
    const float* ow3 = (const float*)d_in[27]; const float* ob3 = (const float*)d_in[28];
    float* out = (float*)d_out;

    DP P; void* p;
    cudaGetSymbolAddress(&p, g_x);     P.x   = (float*)p;
    cudaGetSymbolAddress(&p, g_y);     P.y   = (float*)p;
    cudaGetSymbolAddress(&p, g_ql);    P.ql  = (float*)p;
    cudaGetSymbolAddress(&p, g_vl);    P.vl  = (float*)p;
    cudaGetSymbolAddress(&p, g_att);   P.att = (float*)p;
    cudaGetSymbolAddress(&p, g_x1);    P.x1  = (float*)p;
    cudaGetSymbolAddress(&p, g_h2);    P.h2  = (float*)p;
    cudaGetSymbolAddress(&p, g_xp);    P.xp   = (uint32_t*)p;
    cudaGetSymbolAddress(&p, g_yp);    P.yp   = (uint32_t*)p;
    cudaGetSymbolAddress(&p, g_qlp);   P.qlp  = (uint32_t*)p;
    cudaGetSymbolAddress(&p, g_x1p);   P.x1p  = (uint32_t*)p;
    cudaGetSymbolAddress(&p, g_ctxp);  P.ctxp = (uint32_t*)p;
    cudaGetSymbolAddress(&p, g_ffp);   P.ffp  = (uint32_t*)p;
    cudaGetSymbolAddress(&p, g_hcatp); P.hcatp= (uint32_t*)p;
    cudaGetSymbolAddress(&p, g_h1p);   P.h1p  = (uint32_t*)p;
    cudaGetSymbolAddress(&p, g_Wqp);   P.Wqp  = (uint32_t*)p;
    cudaGetSymbolAddress(&p, g_Wvp);   P.Wvp  = (uint32_t*)p;
    cudaGetSymbolAddress(&p, g_Wop);   P.Wop  = (uint32_t*)p;
    cudaGetSymbolAddress(&p, g_W1p);   P.W1p  = (uint32_t*)p;
    cudaGetSymbolAddress(&p, g_W2p);   P.W2p  = (uint32_t*)p;
    cudaGetSymbolAddress(&p, g_ow1p);  P.ow1p = (uint32_t*)p;
    cudaGetSymbolAddress(&p, g_ow2p);  P.ow2p = (uint32_t*)p;

    // ---- pack all weights to bf16 (stacked: pairs never cross layer bounds) ----
    {
        int kp, n4;
        kp = 6*DD/2;  n4 = DD/4;
        pack_mat4<<<(int)(((size_t)kp*n4 + 255)/256), 256>>>(Wq, P.Wqp, kp, n4);
        pack_mat4<<<(int)(((size_t)kp*n4 + 255)/256), 256>>>(Wv, P.Wvp, kp, n4);
        pack_mat4<<<(int)(((size_t)kp*n4 + 255)/256), 256>>>(Wo, P.Wop, kp, n4);
        kp = 6*DD/2;  n4 = DFF/4;
        pack_mat4<<<(int)(((size_t)kp*n4 + 255)/256), 256>>>(W1, P.W1p, kp, n4);
        kp = 6*DFF/2; n4 = DD/4;
        pack_mat4<<<(int)(((size_t)kp*n4 + 255)/256), 256>>>(W2, P.W2p, kp, n4);
        kp = DD;      n4 = FC1D/4;   // K = 2D
        pack_mat4<<<(int)(((size_t)kp*n4 + 255)/256), 256>>>(ow1, P.ow1p, kp, n4);
        kp = FC1D/2;  n4 = FC2D/4;
        pack_mat4<<<(int)(((size_t)kp*n4 + 255)/256), 256>>>(ow2, P.ow2p, kp, n4);
    }

    embed_kernel<<<NTOK, 256>>>(q_data, target, pid_data, q_embed, qa_embed,
                                q_diff, qa_diff, pid_diff);

    // blocks_1: y = block(y, y, strict=False), layers 0..1
    run_block(P, P.y, P.yp, P.yp, 0, 0, bq, bv, Wg, bo, ln1g, ln1b, b1, b2, ln2g, ln2b);
    run_block(P, P.y, P.yp, P.yp, 0, 1, bq, bv, Wg, bo, ln1g, ln1b, b1, b2, ln2g, ln2b);
    // blocks_2: alternate self (non-strict) / cross-with-y (strict), layers 2..5
    run_block(P, P.x, P.xp, P.xp, 0, 2, bq, bv, Wg, bo, ln1g, ln1b, b1, b2, ln2g, ln2b);
    run_block(P, P.x, P.xp, P.yp, 1, 3, bq, bv, Wg, bo, ln1g, ln1b, b1, b2, ln2g, ln2b);
    run_block(P, P.x, P.xp, P.xp, 0, 4, bq, bv, Wg, bo, ln1g, ln1b, b1, b2, ln2g, ln2b);
    run_block(P, P.x, P.xp, P.yp, 1, 5, bq, bv, Wg, bo, ln1g, ln1b, b1, b2, ln2g, ln2b);

    // output head
    concat_kernel<<<NTOK, 256>>>();
    gemm_bf16<<<dim3(FC1D / 128, NTOK / 128), 256>>>(P.hcatp, P.ow1p, ob1, nullptr, P.h1p, NTOK, FC1D, 2*DD, 1);
    gemm_bf16<<<dim3(FC2D / 128, NTOK / 128), 256>>>(P.h1p, P.ow2p, ob2, P.h2, nullptr, NTOK, FC2D, FC1D, 1);
    final_kernel<<<NTOK / 4, 128>>>(ow3, ob3, out);
}

// round 17
// speedup vs baseline: 1.0028x; 1.0013x over previous
#include <cuda_runtime.h>
#include <math.h>
#include <stdint.h>

#define BB 24
#define SS 512
#define DD 512
#define HH 8
#define DKH 64
#define DFF 2048
#define FC1D 512
#define FC2D 256
#define NTOK (BB*SS)
#define HR 7   /* H - HS routed heads */

// ------------------------- scratch (device globals) -------------------------
__device__ __align__(16) float g_x[NTOK*DD];
__device__ __align__(16) float g_y[NTOK*DD];
__device__ __align__(16) float g_ql[NTOK*DD];
__device__ __align__(16) float g_vl[NTOK*DD];
__device__ __align__(16) float g_att[NTOK*DD];
__device__ __align__(16) float g_x1[NTOK*DD];
__device__ __align__(16) float g_h2[NTOK*FC2D];
__device__ float g_dyn[NTOK*HR];
__device__ float g_rmask[BB*HH];

// packed bf16 mirrors (u32 = pair of bf16 along the consumer-K dim)
__device__ __align__(16) uint32_t g_xp[NTOK*DD/2];
__device__ __align__(16) uint32_t g_yp[NTOK*DD/2];
__device__ __align__(16) uint32_t g_qembp[NTOK*DD/2];
__device__ __align__(16) uint32_t g_qlp[NTOK*DD/2];
__device__ __align__(16) uint32_t g_ctxp[NTOK*DD/2];
__device__ __align__(16) uint32_t g_x1p[NTOK*DD/2];
__device__ __align__(16) uint32_t g_ffp[NTOK*DFF/2];
__device__ __align__(16) uint32_t g_hcatp[NTOK*DD];      // 2D/2 = D u32 per row
__device__ __align__(16) uint32_t g_h1p[NTOK*FC1D/2];

// packed weights
__device__ __align__(16) uint32_t g_Wqp[6*(DD/2)*DD];
__device__ __align__(16) uint32_t g_Wvp[6*(DD/2)*DD];
__device__ __align__(16) uint32_t g_Wop[6*(DD/2)*DD];
__device__ __align__(16) uint32_t g_W1p[6*(DD/2)*DFF];
__device__ __align__(16) uint32_t g_W2p[6*(DFF/2)*DD];
__device__ __align__(16) uint32_t g_ow1p[DD*FC1D];
__device__ __align__(16) uint32_t g_ow2p[(FC1D/2)*FC2D];

// ------------------------- helpers -------------------------
__device__ __forceinline__ uint32_t packbf(float lo, float hi) {
    uint32_t r;
    asm("cvt.rn.bf16x2.f32 %0, %1, %2;" : "=r"(r) : "f"(hi), "f"(lo));  // first src -> high half
    return r;
}

__device__ __forceinline__ void mma_bf16(float c[4], const uint32_t a[4], const uint32_t b[2]) {
    asm volatile(
        "mma.sync.aligned.m16n8k16.row.col.f32.bf16.bf16.f32 "
        "{%0,%1,%2,%3}, {%4,%5,%6,%7}, {%8,%9}, {%0,%1,%2,%3};"
        : "+f"(c[0]), "+f"(c[1]), "+f"(c[2]), "+f"(c[3])
        : "r"(a[0]), "r"(a[1]), "r"(a[2]), "r"(a[3]), "r"(b[0]), "r"(b[1]));
}

__device__ __forceinline__ void cp16(void* dst, const void* src) {
    uint32_t d = (uint32_t)__cvta_generic_to_shared(dst);
    asm volatile("cp.async.cg.shared.global [%0], [%1], 16;" :: "r"(d), "l"(src));
}

// ------------------------- vectorized weight packing -------------------------
// W[K][N] f32 -> out[K/2][N] u32 ; pairs along K. Works on layer-stacked weights
// because per-layer K is even, so pairs never cross layer boundaries.
__global__ void pack_mat4(const float* __restrict__ W, uint32_t* __restrict__ out,
                          int KP, int N4) {
    size_t idx = (size_t)blockIdx.x * 256 + threadIdx.x;
    if (idx >= (size_t)KP * N4) return;
    int n4 = (int)(idx % N4);
    size_t kp = idx / N4;
    int N = N4 * 4;
    float4 r0 = *(const float4*)&W[(2 * kp) * N + (size_t)n4 * 4];
    float4 r1 = *(const float4*)&W[(2 * kp + 1) * N + (size_t)n4 * 4];
    uint4 o;
    o.x = packbf(r0.x, r1.x);
    o.y = packbf(r0.y, r1.y);
    o.z = packbf(r0.z, r1.z);
    o.w = packbf(r0.w, r1.w);
    ((uint4*)out)[idx] = o;
}

// ------------------------- embeddings -------------------------
__global__ void embed_kernel(const int* __restrict__ qd, const int* __restrict__ tg,
                             const int* __restrict__ pid,
                             const float* __restrict__ qtab, const float* __restrict__ qatab,
                             const float* __restrict__ qdtab, const float* __restrict__ qadtab,
                             const float* __restrict__ pdtab) {
    int t = blockIdx.x;
    int tid = threadIdx.x;              // blockDim = 256
    int d0 = 2 * tid, d1 = d0 + 1;
    int qi = qd[t], ti = tg[t], pi = pid[t];
    float ps = pdtab[pi];
    float qe0 = qtab[(size_t)qi*DD + d0], qe1 = qtab[(size_t)qi*DD + d1];
    float qv0 = qdtab[(size_t)qi*DD + d0], qv1 = qdtab[(size_t)qi*DD + d1];
    float em0 = qe0 + ps * qv0, em1 = qe1 + ps * qv1;
    float qa0 = qatab[(size_t)ti*DD + d0] + qe0 + ps * (qadtab[(size_t)ti*DD + d0] + qv0);
    float qa1 = qatab[(size_t)ti*DD + d1] + qe1 + ps * (qadtab[(size_t)ti*DD + d1] + qv1);
    g_x[(size_t)t*DD + d0] = em0; g_x[(size_t)t*DD + d1] = em1;
    g_y[(size_t)t*DD + d0] = qa0; g_y[(size_t)t*DD + d1] = qa1;
    g_xp[(size_t)t*(DD/2) + tid]    = packbf(em0, em1);
    g_yp[(size_t)t*(DD/2) + tid]    = packbf(qa0, qa1);
    g_qembp[(size_t)t*(DD/2) + tid] = packbf(em0, em1);
}

// ------------------------- bf16 tensor-core GEMM, 2-stage cp.async pipeline -------------------------
__global__ __launch_bounds__(256) void gemm_bf16(const uint32_t* __restrict__ Apk,
                                                 const uint32_t* __restrict__ Bpk,
                                                 const float* __restrict__ bias,
                                                 float* __restrict__ C, uint32_t* __restrict__ Cpk,
                                                 int M, int N, int K, int relu) {
    __shared__ uint32_t As[2][128][20];
    __shared__ uint32_t Bs[2][16][136];
    int tid = threadIdx.x;
    int lane = tid & 31, warp = tid >> 5;
    int wm = warp >> 1, wn = warp & 1;
    int g = lane >> 2, tg = lane & 3;
    int m0 = blockIdx.y * 128, n0 = blockIdx.x * 128;
    int KP = K >> 1;
    int NK = K >> 5;

    float acc[2][8][4];
    #pragma unroll
    for (int i = 0; i < 2; i++)
        #pragma unroll
        for (int j = 0; j < 8; j++)
            #pragma unroll
            for (int r = 0; r < 4; r++) acc[i][j][r] = 0.0f;

#define LOAD_TILES(st, it) do {                                                   \
    int base = (it) * 16;                                                         \
    _Pragma("unroll")                                                             \
    for (int p = 0; p < 2; p++) {                                                 \
        int id = tid + p * 256; int r = id >> 2; int c4 = (id & 3) * 4;           \
        cp16(&As[st][r][c4], &Apk[(size_t)(m0 + r) * KP + base + c4]);            \
    }                                                                             \
    _Pragma("unroll")                                                             \
    for (int p = 0; p < 2; p++) {                                                 \
        int id = tid + p * 256; int r = id >> 5; int c4 = (id & 31) * 4;          \
        cp16(&Bs[st][r][c4], &Bpk[(size_t)(base + r) * N + n0 + c4]);             \
    }                                                                             \
    asm volatile("cp.async.commit_group;");                                       \
} while (0)

    LOAD_TILES(0, 0);
    int s = 0;
    for (int it = 0; it < NK; it++) {
        if (it + 1 < NK) {
            LOAD_TILES(s ^ 1, it + 1);
            asm volatile("cp.async.wait_group 1;");
        } else {
            asm volatile("cp.async.wait_group 0;");
        }
        __syncthreads();
        #pragma unroll
        for (int kk = 0; kk < 2; kk++) {
            int kb = kk * 8;
            uint32_t af[2][4], bf[8][2];
            #pragma unroll
            for (int i = 0; i < 2; i++) {
                int m = wm * 32 + i * 16;
                af[i][0] = As[s][m + g][kb + tg];
                af[i][1] = As[s][m + 8 + g][kb + tg];
                af[i][2] = As[s][m + g][kb + 4 + tg];
                af[i][3] = As[s][m + 8 + g][kb + 4 + tg];
            }
            #pragma unroll
            for (int j = 0; j < 8; j++) {
                int n = wn * 64 + j * 8 + g;
                bf[j][0] = Bs[s][kb + tg][n];
                bf[j][1] = Bs[s][kb + 4 + tg][n];
            }
            #pragma unroll
            for (int i = 0; i < 2; i++)
                #pragma unroll
                for (int j = 0; j < 8; j++)
                    mma_bf16(acc[i][j], af[i], bf[j]);
        }
        __syncthreads();
        s ^= 1;
    }
#undef LOAD_TILES

    #pragma unroll
    for (int i = 0; i < 2; i++) {
        int m = m0 + wm * 32 + i * 16 + g;
        #pragma unroll
        for (int j = 0; j < 8; j++) {
            int n = n0 + wn * 64 + j * 8 + tg * 2;
            float b0 = bias[n], b1 = bias[n + 1];
            float v0 = acc[i][j][0] + b0, v1 = acc[i][j][1] + b1;
            float v2 = acc[i][j][2] + b0, v3 = acc[i][j][3] + b1;
            if (relu) { v0 = fmaxf(v0, 0.f); v1 = fmaxf(v1, 0.f); v2 = fmaxf(v2, 0.f); v3 = fmaxf(v3, 0.f); }
            if (C) {
                C[(size_t)m * N + n]           = v0;
                C[(size_t)m * N + n + 1]       = v1;
                C[(size_t)(m + 8) * N + n]     = v2;
                C[(size_t)(m + 8) * N + n + 1] = v3;
            }
            if (Cpk) {
                Cpk[(size_t)m * (N >> 1) + (n >> 1)]       = packbf(v0, v1);
                Cpk[(size_t)(m + 8) * (N >> 1) + (n >> 1)] = packbf(v2, v3);
            }
        }
    }
}

// ------------------------- fused flash attention -------------------------
// One CTA = 128 query rows of one (b,h). 8 warps x 16 rows. Online softmax.
// K == Q (kq_same). Causal early-exit over 64-wide j-tiles. Writes g_ctxp packed.
// Token-row-0 (uniform softmax) is overwritten afterwards by row0_fix.
__global__ __launch_bounds__(256) void flash_attn(const float* __restrict__ vl, int strict) {
    int bh = blockIdx.y; int b = bh >> 3, h = bh & 7;
    int i0 = blockIdx.x * 128;
    __shared__ uint32_t Qs[128][36];   // [row][dkpair]
    __shared__ uint32_t Ks[64][36];    // [row][dkpair]  (same layout as Qs)
    __shared__ uint32_t Vs[32][72];    // [jpair][dk]
    int tid = threadIdx.x, lane = tid & 31, w = tid >> 5;
    int g = lane >> 2, tg = lane & 3;

    // load Q tile (coalesced, conflict-free)
    #pragma unroll
    for (int p = 0; p < 16; p++) {
        int id = tid + p * 256;
        int r = id >> 5, c = id & 31;
        Qs[r][c] = g_qlp[(size_t)(b * SS + i0 + r) * (DD/2) + h * 32 + c];
    }

    float oacc[8][4];
    #pragma unroll
    for (int d = 0; d < 8; d++)
        #pragma unroll
        for (int r = 0; r < 4; r++) oacc[d][r] = 0.0f;
    float m0 = -1e30f, m1 = -1e30f, l0 = 0.0f, l1 = 0.0f;

    int row0g = i0 + w * 16 + g;   // global seq row for c0/c1 of fragments
    int row1g = row0g + 8;

    int njt = 2 * blockIdx.x + 2;  // causal tile limit: j0 <= i0+127

    for (int jt = 0; jt < njt; jt++) {
        int j0 = jt * 64;
        __syncthreads();           // previous iter's K/V fully consumed
        // K tile: 64 rows x 32 dkpairs
        #pragma unroll
        for (int p = 0; p < 8; p++) {
            int id = tid + p * 256;
            int r = id >> 5, c = id & 31;
            Ks[r][c] = g_qlp[(size_t)(b * SS + j0 + r) * (DD/2) + h * 32 + c];
        }
        // V tile: pack fp32 rows pairs -> Vs[jpair][dk]
        #pragma unroll
        for (int p = 0; p < 2; p++) {
            int id = tid + p * 256;
            int jp = id >> 4, c = (id & 15) * 4;
            const float* v0p = &vl[(size_t)(b * SS + j0 + 2 * jp) * DD + h * DKH + c];
            const float* v1p = v0p + DD;
            float4 a = *(const float4*)v0p;
            float4 bb = *(const float4*)v1p;
            Vs[jp][c + 0] = packbf(a.x, bb.x);
            Vs[jp][c + 1] = packbf(a.y, bb.y);
            Vs[jp][c + 2] = packbf(a.z, bb.z);
            Vs[jp][c + 3] = packbf(a.w, bb.w);
        }
        __syncthreads();

        // ---- scores: S[16x64] per warp ----
        float sacc[8][4];
        #pragma unroll
        for (int jf = 0; jf < 8; jf++)
            #pragma unroll
            for (int r = 0; r < 4; r++) sacc[jf][r] = 0.0f;
        #pragma unroll
        for (int kc = 0; kc < 4; kc++) {
            uint32_t af[4];
            af[0] = Qs[w * 16 + g][kc * 8 + tg];
            af[1] = Qs[w * 16 + 8 + g][kc * 8 + tg];
            af[2] = Qs[w * 16 + g][kc * 8 + 4 + tg];
            af[3] = Qs[w * 16 + 8 + g][kc * 8 + 4 + tg];
            #pragma unroll
            for (int jf = 0; jf < 8; jf++) {
                uint32_t bf2[2];
                bf2[0] = Ks[jf * 8 + g][kc * 8 + tg];
                bf2[1] = Ks[jf * 8 + g][kc * 8 + 4 + tg];
                mma_bf16(sacc[jf], af, bf2);
            }
        }

        // ---- mask + scale, tile row-max ----
        float tm0 = -1e30f, tm1 = -1e30f;
        #pragma unroll
        for (int jf = 0; jf < 8; jf++) {
            int c0 = j0 + jf * 8 + 2 * tg;
            int c1 = c0 + 1;
            bool a00 = strict ? (c0 < row0g || (row0g == 0 && c0 == 0)) : (c0 <= row0g);
            bool a01 = strict ? (c1 < row0g) : (c1 <= row0g);
            bool a10 = strict ? (c0 < row1g) : (c0 <= row1g);
            bool a11 = strict ? (c1 < row1g) : (c1 <= row1g);
            sacc[jf][0] = a00 ? sacc[jf][0] * 0.125f : -1e30f;
            sacc[jf][1] = a01 ? sacc[jf][1] * 0.125f : -1e30f;
            sacc[jf][2] = a10 ? sacc[jf][2] * 0.125f : -1e30f;
            sacc[jf][3] = a11 ? sacc[jf][3] * 0.125f : -1e30f;
            tm0 = fmaxf(tm0, fmaxf(sacc[jf][0], sacc[jf][1]));
            tm1 = fmaxf(tm1, fmaxf(sacc[jf][2], sacc[jf][3]));
        }
        tm0 = fmaxf(tm0, __shfl_xor_sync(0xffffffffu, tm0, 1));
        tm0 = fmaxf(tm0, __shfl_xor_sync(0xffffffffu, tm0, 2));
        tm1 = fmaxf(tm1, __shfl_xor_sync(0xffffffffu, tm1, 1));
        tm1 = fmaxf(tm1, __shfl_xor_sync(0xffffffffu, tm1, 2));

        float nm0 = fmaxf(m0, tm0), nm1 = fmaxf(m1, tm1);
        float sc0 = expf(m0 - nm0), sc1 = expf(m1 - nm1);
        float ts0 = 0.0f, ts1 = 0.0f;
        #pragma unroll
        for (int jf = 0; jf < 8; jf++) {
            float p0 = expf(sacc[jf][0] - nm0);
            float p1 = expf(sacc[jf][1] - nm0);
            float p2 = expf(sacc[jf][2] - nm1);
            float p3 = expf(sacc[jf][3] - nm1);
            sacc[jf][0] = p0; sacc[jf][1] = p1; sacc[jf][2] = p2; sacc[jf][3] = p3;
            ts0 += p0 + p1; ts1 += p2 + p3;
        }
        ts0 += __shfl_xor_sync(0xffffffffu, ts0, 1);
        ts0 += __shfl_xor_sync(0xffffffffu, ts0, 2);
        ts1 += __shfl_xor_sync(0xffffffffu, ts1, 1);
        ts1 += __shfl_xor_sync(0xffffffffu, ts1, 2);
        l0 = l0 * sc0 + ts0;
        l1 = l1 * sc1 + ts1;
        m0 = nm0; m1 = nm1;
        #pragma unroll
        for (int d = 0; d < 8; d++) {
            oacc[d][0] *= sc0; oacc[d][1] *= sc0;
            oacc[d][2] *= sc1; oacc[d][3] *= sc1;
        }

        // ---- P @ V: C-frag of scores re-packed as A-frag ----
        #pragma unroll
        for (int kc = 0; kc < 4; kc++) {
            uint32_t af[4];
            af[0] = packbf(sacc[2*kc][0],   sacc[2*kc][1]);
            af[1] = packbf(sacc[2*kc][2],   sacc[2*kc][3]);
            af[2] = packbf(sacc[2*kc+1][0], sacc[2*kc+1][1]);
            af[3] = packbf(sacc[2*kc+1][2], sacc[2*kc+1][3]);
            #pragma unroll
            for (int df = 0; df < 8; df++) {
                uint32_t bf2[2];
                bf2[0] = Vs[kc * 8 + tg][df * 8 + g];
                bf2[1] = Vs[kc * 8 + 4 + tg][df * 8 + g];
                mma_bf16(oacc[df], af, bf2);
            }
        }
    }

    float rm = g_rmask[bh];
    float inv0 = rm / l0, inv1 = rm / l1;
    #pragma unroll
    for (int df = 0; df < 8; df++) {
        int dkp = df * 4 + tg;   // pair index: cols df*8+2tg, +1
        g_ctxp[(size_t)(b * SS + row0g) * (DD/2) + h * 32 + dkp] = packbf(oacc[df][0] * inv0, oacc[df][1] * inv0);
        g_ctxp[(size_t)(b * SS + row1g) * (DD/2) + h * 32 + dkp] = packbf(oacc[df][2] * inv1, oacc[df][3] * inv1);
    }
}

// row 0 of each (b,h): uniform attention over all 512 keys -> mean(V) * rmask
__global__ void row0_fix(const float* __restrict__ vl) {
    int bh = blockIdx.x; int b = bh >> 3, h = bh & 7;
    __shared__ float red[256];
    __shared__ float outv[64];
    int tid = threadIdx.x;
    int dk = tid & 63, chunk = tid >> 6;     // 4 chunks x 128 rows
    float s = 0.0f;
    for (int j = chunk * 128; j < chunk * 128 + 128; j++)
        s += vl[(size_t)(b * SS + j) * DD + h * DKH + dk];
    red[tid] = s; __syncthreads();
    if (tid < 64)
        outv[tid] = (red[tid] + red[tid + 64] + red[tid + 128] + red[tid + 192])
                    * (1.0f / 512.0f) * g_rmask[bh];
    __syncthreads();
    if (tid < 32)
        g_ctxp[(size_t)(b * SS) * (DD/2) + h * 32 + tid] = packbf(outv[2 * tid], outv[2 * tid + 1]);
}

// ------------------------- router -------------------------
__global__ void router_kernel(const float* __restrict__ Wg) {
    int warp = (blockIdx.x * blockDim.x + threadIdx.x) >> 5;
    int lane = threadIdx.x & 31;
    if (warp >= NTOK) return;
    const float* xrow = g_ql + (size_t)warp * DD;
    float acc[HR];
    #pragma unroll
    for (int o = 0; o < HR; o++) acc[o] = 0.0f;
    #pragma unroll 4
    for (int c = 0; c < 16; c++) {
        int k = c * 32 + lane;
        float a = xrow[k];
        #pragma unroll
        for (int o = 0; o < HR; o++) acc[o] += a * Wg[k * HR + o];
    }
    #pragma unroll
    for (int o = 0; o < HR; o++)
        #pragma unroll
        for (int off = 16; off; off >>= 1)
            acc[o] += __shfl_xor_sync(0xffffffffu, acc[o], off);
    float mx = acc[0];
    #pragma unroll
    for (int o = 1; o < HR; o++) mx = fmaxf(mx, acc[o]);
    float g[HR], s = 0.0f;
    #pragma unroll
    for (int o = 0; o < HR; o++) { g[o] = expf(acc[o] - mx); s += g[o]; }
    float inv = 1.0f / s;
    #pragma unroll
    for (int o = 0; o < HR; o++) g[o] *= inv;
    int i1 = 0;
    #pragma unroll
    for (int o = 1; o < HR; o++) if (g[o] > g[i1]) i1 = o;
    int i2 = (i1 == 0) ? 1 : 0;
    #pragma unroll
    for (int o = 0; o < HR; o++) if (o != i1 && o != i2 && g[o] > g[i2]) i2 = o;
    if (lane < HR)
        g_dyn[(size_t)warp * HR + lane] = (lane == i1 || lane == i2) ? g[lane] : 0.0f;
}

// ------------------------- rmask -------------------------
__global__ void rmask_kernel() {
    int b = blockIdx.x / HR, o = blockIdx.x % HR;
    __shared__ float red[256];
    int tid = threadIdx.x;
    float s = 0.0f;
    for (int si = tid; si < SS; si += 256)
        s += g_dyn[((size_t)b * SS + si) * HR + o];
    red[tid] = s; __syncthreads();
    for (int st = 128; st; st >>= 1) { if (tid < st) red[tid] += red[tid + st]; __syncthreads(); }
    if (tid == 0) {
        g_rmask[b * HH + 1 + o] = red[0] * (1.0f / SS);
        if (o == 0) g_rmask[b * HH] = 1.0f;
    }
}

// ------------------------- fused residual add + layernorm (+packed mirror) -------------------------
__global__ __launch_bounds__(256) void add_ln(const float* __restrict__ X, const float* __restrict__ A,
                                              const float* __restrict__ gam, const float* __restrict__ bet,
                                              float* __restrict__ outf, uint32_t* __restrict__ outp) {
    int t = blockIdx.x;
    int tid = threadIdx.x;
    int d0 = 2 * tid, d1 = d0 + 1;
    __shared__ float red[256];
    float v0 = X[(size_t)t*DD + d0] + A[(size_t)t*DD + d0];
    float v1 = X[(size_t)t*DD + d1] + A[(size_t)t*DD + d1];
    red[tid] = v0 + v1; __syncthreads();
    for (int s = 128; s; s >>= 1) { if (tid < s) red[tid] += red[tid + s]; __syncthreads(); }
    float mean = red[0] * (1.0f / DD); __syncthreads();
    float e0 = v0 - mean, e1 = v1 - mean;
    red[tid] = e0 * e0 + e1 * e1; __syncthreads();
    for (int s = 128; s; s >>= 1) { if (tid < s) red[tid] += red[tid + s]; __syncthreads(); }
    float inv = rsqrtf(red[0] * (1.0f / DD) + 1e-5f);
    float o0 = e0 * inv * gam[d0] + bet[d0];
    float o1 = e1 * inv * gam[d1] + bet[d1];
    outf[(size_t)t*DD + d0] = o0;
    outf[(size_t)t*DD + d1] = o1;
    outp[(size_t)t*(DD/2) + tid] = packbf(o0, o1);
}

// ------------------------- output-head helpers -------------------------
__global__ void concat_kernel() {
    int t = blockIdx.x, tid = threadIdx.x;   // blockDim = 256
    g_hcatp[(size_t)t * DD + tid]            = g_xp[(size_t)t * (DD/2) + tid];
    g_hcatp[(size_t)t * DD + (DD/2) + tid]   = g_qembp[(size_t)t * (DD/2) + tid];
}

__global__ void final_kernel(const float* __restrict__ ow3, const float* __restrict__ ob3,
                             float* __restrict__ out) {
    int warp = (blockIdx.x * blockDim.x + threadIdx.x) >> 5;
    int lane = threadIdx.x & 31;
    if (warp >= NTOK) return;
    float s = 0.0f;
    #pragma unroll
    for (int c = 0; c < 8; c++) {
        int k = c * 32 + lane;
        s += g_h2[(size_t)warp * FC2D + k] * ow3[k];
    }
    #pragma unroll
    for (int off = 16; off; off >>= 1) s += __shfl_xor_sync(0xffffffffu, s, off);
    if (lane == 0) {
        float z = s + ob3[0];
        out[warp] = 1.0f / (1.0f + expf(-z));
    }
}

// ------------------------- host orchestration -------------------------
struct DP {
    float *x, *y, *ql, *vl, *att, *x1, *h2;
    uint32_t *xp, *yp, *qlp, *x1p, *ctxp, *ffp, *hcatp, *h1p;
    uint32_t *Wqp, *Wvp, *Wop, *W1p, *W2p, *ow1p, *ow2p;
};

static void run_block(const DP& P, float* xqf, uint32_t* xqp, const uint32_t* xvp,
                      int strict, int layer,
                      const float* bq, const float* bv, const float* Wg, const float* bo,
                      const float* ln1g, const float* ln1b,
                      const float* b1, const float* b2,
                      const float* ln2g, const float* ln2b) {
    const uint32_t* wqp = P.Wqp + (size_t)layer * (DD/2) * DD;
    const uint32_t* wvp = P.Wvp + (size_t)layer * (DD/2) * DD;
    const uint32_t* wop = P.Wop + (size_t)layer * (DD/2) * DD;
    const uint32_t* w1p = P.W1p + (size_t)layer * (DD/2) * DFF;
    const uint32_t* w2p = P.W2p + (size_t)layer * (DFF/2) * DD;
    const float* wg  = Wg + (size_t)layer * DD * HR;
    const float* pbq = bq + (size_t)layer * DD;
    const float* pbv = bv + (size_t)layer * DD;
    const float* pbo = bo + (size_t)layer * DD;
    const float* pb1 = b1 + (size_t)layer * DFF;
    const float* pb2 = b2 + (size_t)layer * DD;
    const float* g1 = ln1g + (size_t)layer * DD; const float* be1 = ln1b + (size_t)layer * DD;
    const float* g2 = ln2g + (size_t)layer * DD; const float* be2 = ln2b + (size_t)layer * DD;

    dim3 gproj(DD / 128, NTOK / 128);
    gemm_bf16<<<gproj, 256>>>(xqp, wqp, pbq, P.ql, P.qlp, NTOK, DD, DD, 0);
    gemm_bf16<<<gproj, 256>>>(xvp, wvp, pbv, P.vl, nullptr, NTOK, DD, DD, 0);
    router_kernel<<<NTOK / 4, 128>>>(wg);
    rmask_kernel<<<BB * HR, 256>>>();
    flash_attn<<<dim3(SS / 128, BB * HH), 256>>>(P.vl, strict);
    row0_fix<<<BB * HH, 256>>>(P.vl);
    gemm_bf16<<<gproj, 256>>>(P.ctxp, wop, pbo, P.att, nullptr, NTOK, DD, DD, 0);
    add_ln<<<NTOK, 256>>>(xqf, P.att, g1, be1, P.x1, P.x1p);
    gemm_bf16<<<dim3(DFF / 128, NTOK / 128), 256>>>(P.x1p, w1p, pb1, nullptr, P.ffp, NTOK, DFF, DD, 1);
    gemm_bf16<<<gproj, 256>>>(P.ffp, w2p, pb2, P.att, nullptr, NTOK, DD, DFF, 0);
    add_ln<<<NTOK, 256>>>(P.x1, P.att, g2, be2, xqf, xqp);
}

extern "C" void kernel_launch(void* const* d_in, const int* in_sizes, int n_in,
                              void* d_out, int out_size) {
    const int*   q_data   = (const int*)d_in[0];
    const int*   target   = (const int*)d_in[1];
    const int*   pid_data = (const int*)d_in[2];
    const float* q_embed  = (const float*)d_in[3];
    const float* qa_embed = (const float*)d_in[4];
    const float* q_diff   = (const float*)d_in[5];
    const float* qa_diff  = (const float*)d_in[6];
    const float* pid_diff = (const float*)d_in[7];
    const float* Wq = (const float*)d_in[8];   const float* bq = (const float*)d_in[9];
    const float* Wv = (const float*)d_in[10];  const float* bv = (const float*)d_in[11];
    const float* Wg = (const float*)d_in[12];
    const float* Wo = (const float*)d_in[13];  const float* bo = (const float*)d_in[14];
    const float* ln1g = (const float*)d_in[15]; const float* ln1b = (const float*)d_in[16];
    const float* W1 = (const float*)d_in[17];  const float* b1 = (const float*)d_in[18];
    const float* W2 = (const float*)d_in[19];  const float* b2 = (const float*)d_in[20];
    const float* ln2g = (const float*)d_in[21]; const float* ln2b = (const float*)d_in[22];
    const float* ow1 = (const float*)d_in[23]; const float* ob1 = (const float*)d_in[24];
    const float* ow2 = (const float*)d_in[25]; const float* ob2 = (const float*)d_in[26];
    const float* ow3 = (const float*)d_in[27]; const float* ob3 = (const float*)d_in[28];
    float* out = (float*)d_out;

    DP P; void* p;
    cudaGetSymbolAddress(&p, g_x);     P.x   = (float*)p;
    cudaGetSymbolAddress(&p, g_y);     P.y   = (float*)p;
    cudaGetSymbolAddress(&p, g_ql);    P.ql  = (float*)p;
    cudaGetSymbolAddress(&p, g_vl);    P.vl  = (float*)p;
    cudaGetSymbolAddress(&p, g_att);   P.att = (float*)p;
    cudaGetSymbolAddress(&p, g_x1);    P.x1  = (float*)p;
    cudaGetSymbolAddress(&p, g_h2);    P.h2  = (float*)p;
    cudaGetSymbolAddress(&p, g_xp);    P.xp   = (uint32_t*)p;
    cudaGetSymbolAddress(&p, g_yp);    P.yp   = (uint32_t*)p;
    cudaGetSymbolAddress(&p, g_qlp);   P.qlp  = (uint32_t*)p;
    cudaGetSymbolAddress(&p, g_x1p);   P.x1p  = (uint32_t*)p;
    cudaGetSymbolAddress(&p, g_ctxp);  P.ctxp = (uint32_t*)p;
    cudaGetSymbolAddress(&p, g_ffp);   P.ffp  = (uint32_t*)p;
    cudaGetSymbolAddress(&p, g_hcatp); P.hcatp= (uint32_t*)p;
    cudaGetSymbolAddress(&p, g_h1p);   P.h1p  = (uint32_t*)p;
    cudaGetSymbolAddress(&p, g_Wqp);   P.Wqp  = (uint32_t*)p;
    cudaGetSymbolAddress(&p, g_Wvp);   P.Wvp  = (uint32_t*)p;
    cudaGetSymbolAddress(&p, g_Wop);   P.Wop  = (uint32_t*)p;
    cudaGetSymbolAddress(&p, g_W1p);   P.W1p  = (uint32_t*)p;
    cudaGetSymbolAddress(&p, g_W2p);   P.W2p  = (uint32_t*)p;
    cudaGetSymbolAddress(&p, g_ow1p);  P.ow1p = (uint32_t*)p;
    cudaGetSymbolAddress(&p, g_ow2p);  P.ow2p = (uint32_t*)p;

    // ---- pack all weights to bf16 (stacked: pairs never cross layer bounds) ----
    {
        int kp, n4;
        kp = 6*DD/2;  n4 = DD/4;
        pack_mat4<<<(int)(((size_t)kp*n4 + 255)/256), 256>>>(Wq, P.Wqp, kp, n4);
        pack_mat4<<<(int)(((size_t)kp*n4 + 255)/256), 256>>>(Wv, P.Wvp, kp, n4);
        pack_mat4<<<(int)(((size_t)kp*n4 + 255)/256), 256>>>(Wo, P.Wop, kp, n4);
        kp = 6*DD/2;  n4 = DFF/4;
        pack_mat4<<<(int)(((size_t)kp*n4 + 255)/256), 256>>>(W1, P.W1p, kp, n4);
        kp = 6*DFF/2; n4 = DD/4;
        pack_mat4<<<(int)(((size_t)kp*n4 + 255)/256), 256>>>(W2, P.W2p, kp, n4);
        kp = DD;      n4 = FC1D/4;   // K = 2D
        pack_mat4<<<(int)(((size_t)kp*n4 + 255)/256), 256>>>(ow1, P.ow1p, kp, n4);
        kp = FC1D/2;  n4 = FC2D/4;
        pack_mat4<<<(int)(((size_t)kp*n4 + 255)/256), 256>>>(ow2, P.ow2p, kp, n4);
    }

    embed_kernel<<<NTOK, 256>>>(q_data, target, pid_data, q_embed, qa_embed,
                                q_diff, qa_diff, pid_diff);

    // blocks_1: y = block(y, y, strict=False), layers 0..1
    run_block(P, P.y, P.yp, P.yp, 0, 0, bq, bv, Wg, bo, ln1g, ln1b, b1, b2, ln2g, ln2b);
    run_block(P, P.y, P.yp, P.yp, 0, 1, bq, bv, Wg, bo, ln1g, ln1b, b1, b2, ln2g, ln2b);
    // blocks_2: alternate self (non-strict) / cross-with-y (strict), layers 2..5
    run_block(P, P.x, P.xp, P.xp, 0, 2, bq, bv, Wg, bo, ln1g, ln1b, b1, b2, ln2g, ln2b);
    run_block(P, P.x, P.xp, P.yp, 1, 3, bq, bv, Wg, bo, ln1g, ln1b, b1, b2, ln2g, ln2b);
    run_block(P, P.x, P.xp, P.xp, 0, 4, bq, bv, Wg, bo, ln1g, ln1b, b1, b2, ln2g, ln2b);
    run_block(P, P.x, P.xp, P.yp, 1, 5, bq, bv, Wg, bo, ln1g, ln1b, b1, b2, ln2g, ln2b);

    // output head
    concat_kernel<<<NTOK, 256>>>();
    gemm_bf16<<<dim3(FC1D / 128, NTOK / 128), 256>>>(P.hcatp, P.ow1p, ob1, nullptr, P.h1p, NTOK, FC1D, 2*DD, 1);
    gemm_bf16<<<dim3(FC2D / 128, NTOK / 128), 256>>>(P.h1p, P.ow2p, ob2, P.h2, nullptr, NTOK, FC2D, FC1D, 1);
    final_kernel<<<NTOK / 4, 128>>>(ow3, ob3, out);
}